// round 9
// baseline (speedup 1.0000x reference)
#include <cuda_runtime.h>
#include <cuda_fp16.h>
#include <cstdint>

// ---------------------------------------------------------------------------
// CorrBlock: pooled-fmap2 fp16 HMMA GEMM (1-pass: Ahi*Bhi) + warp sampler.
// corr = (1/16) * f1^T f2cat ≈ (1/16)(Ahi*Bhi), fp32 acc, fp16 store.
// Round 9: GEMM CTA 128x128 with 4 warps @ 64x64 (best ldsm/MAC ratio) and
// 2 CTAs/SM (launch_bounds(128,2)) -> tensor-bound instead of LSU-bound.
// ---------------------------------------------------------------------------

#define Bb 2
#define Cc 256
#define HH 64
#define WW 64
#define NN 8
#define QTOT 5440
#define QPAD 5632      // 44 N-tiles of 128
#define PTOT 4096      // H*W

// Scratch (no cudaMalloc allowed)
__device__ float g_f2cat[Bb * Cc * QTOT];                 // 11.1 MB
__device__ __half g_Ah[(size_t)Bb * PTOT * 256];          // 4.2 MB  [m][hi]
__device__ __half g_Bh[(size_t)Bb * QPAD * 256];          // 5.7 MB  [q][hi]
__device__ __half g_corrh[(size_t)Bb * PTOT * QTOT];      // 89 MB   fp16 corr

#define SWZ(o) ((o) ^ (((o) >> 3) & 0x70))

__device__ __forceinline__ uint32_t smem_to_u32(const void* p) {
    uint32_t a;
    asm("{ .reg .u64 t; cvta.to.shared.u64 t, %1; cvt.u32.u64 %0, t; }" : "=r"(a) : "l"(p));
    return a;
}
__device__ __forceinline__ void cp_async16(uint32_t dst, const void* src) {
    asm volatile("cp.async.cg.shared.global [%0], [%1], 16;" :: "r"(dst), "l"(src));
}
__device__ __forceinline__ void ldsm_x4(uint32_t* r, uint32_t addr) {
    asm volatile("ldmatrix.sync.aligned.m8n8.x4.shared.b16 {%0,%1,%2,%3}, [%4];"
                 : "=r"(r[0]), "=r"(r[1]), "=r"(r[2]), "=r"(r[3]) : "r"(addr));
}
__device__ __forceinline__ void mma16816(float* d, const uint32_t* a, uint32_t b0, uint32_t b1) {
    asm volatile("mma.sync.aligned.m16n8k16.row.col.f32.f16.f16.f32 "
                 "{%0,%1,%2,%3}, {%4,%5,%6,%7}, {%8,%9}, {%0,%1,%2,%3};"
                 : "+f"(d[0]), "+f"(d[1]), "+f"(d[2]), "+f"(d[3])
                 : "r"(a[0]), "r"(a[1]), "r"(a[2]), "r"(a[3]), "r"(b0), "r"(b1));
}

// ---------------------------------------------------------------------------
// Kernel 1: pool fmap2 into 4 levels, concatenated along q. grid (C, B), 256t.
// ---------------------------------------------------------------------------
__global__ __launch_bounds__(256) void pool_kernel(const float* __restrict__ f2) {
    int c = blockIdx.x, b = blockIdx.y;
    const float* in = f2 + ((size_t)b * Cc + c) * (HH * WW);
    float* outp = g_f2cat + ((size_t)b * Cc + c) * QTOT;
    __shared__ float s0[4096];
    __shared__ float s1[1024];
    __shared__ float s2[256];
    int tid = threadIdx.x;
    for (int i = tid; i < 1024; i += 256) {
        float4 v = ((const float4*)in)[i];
        ((float4*)s0)[i] = v;
        ((float4*)outp)[i] = v;
    }
    __syncthreads();
    for (int o = tid; o < 1024; o += 256) {
        int y = o >> 5, x = o & 31;
        float v = 0.25f * (s0[(2*y)*64 + 2*x] + s0[(2*y)*64 + 2*x + 1]
                         + s0[(2*y+1)*64 + 2*x] + s0[(2*y+1)*64 + 2*x + 1]);
        s1[o] = v; outp[4096 + o] = v;
    }
    __syncthreads();
    if (tid < 256) {
        int y = tid >> 4, x = tid & 15;
        float v = 0.25f * (s1[(2*y)*32 + 2*x] + s1[(2*y)*32 + 2*x + 1]
                         + s1[(2*y+1)*32 + 2*x] + s1[(2*y+1)*32 + 2*x + 1]);
        s2[tid] = v; outp[5120 + tid] = v;
    }
    __syncthreads();
    if (tid < 64) {
        int y = tid >> 3, x = tid & 7;
        float v = 0.25f * (s2[(2*y)*16 + 2*x] + s2[(2*y)*16 + 2*x + 1]
                         + s2[(2*y+1)*16 + 2*x] + s2[(2*y+1)*16 + 2*x + 1]);
        outp[5376 + tid] = v;
    }
}

// ---------------------------------------------------------------------------
// Kernel 2a: transpose f1 [b][c][p] -> fp16 hi [b][p][256]
// ---------------------------------------------------------------------------
__global__ __launch_bounds__(256) void aprep_kernel(const float* __restrict__ f1) {
    __shared__ float tile[32][33];
    int b = blockIdx.z, p0 = blockIdx.x * 32, c0 = blockIdx.y * 32;
    int tx = threadIdx.x, ty = threadIdx.y;
#pragma unroll
    for (int k = 0; k < 4; k++) {
        int c = c0 + ty + 8 * k;
        tile[ty + 8 * k][tx] = f1[((size_t)b * Cc + c) * PTOT + p0 + tx];
    }
    __syncthreads();
#pragma unroll
    for (int k = 0; k < 4; k++) {
        int p = p0 + ty + 8 * k, c = c0 + tx;
        g_Ah[((size_t)b * PTOT + p) * 256 + c] = __float2half_rn(tile[tx][ty + 8 * k]);
    }
}

// ---------------------------------------------------------------------------
// Kernel 2b: transpose g_f2cat [b][c][q] -> fp16 hi [b][q][256], pad q>=5440
// ---------------------------------------------------------------------------
__global__ __launch_bounds__(256) void bprep_kernel() {
    __shared__ float tile[32][33];
    int b = blockIdx.z, q0 = blockIdx.x * 32, c0 = blockIdx.y * 32;
    int tx = threadIdx.x, ty = threadIdx.y;
#pragma unroll
    for (int k = 0; k < 4; k++) {
        int c = c0 + ty + 8 * k, q = q0 + tx;
        tile[ty + 8 * k][tx] = (q < QTOT) ? g_f2cat[((size_t)b * Cc + c) * QTOT + q] : 0.f;
    }
    __syncthreads();
#pragma unroll
    for (int k = 0; k < 4; k++) {
        int q = q0 + ty + 8 * k, c = c0 + tx;
        g_Bh[((size_t)b * QPAD + q) * 256 + c] = __float2half_rn(tile[tx][ty + 8 * k]);
    }
}

// ---------------------------------------------------------------------------
// Kernel 3: HMMA GEMM. CTA 128(M) x 128(N), BK=64 halves, K'=256 (4 chunks),
// 128 threads / 4 warps (warp tile 64x64, acc 128 regs), 3-stage cp.async,
// __launch_bounds__(128,2) -> 2 CTAs/SM. grid (44, 32, 2).
// ---------------------------------------------------------------------------
#define GT 128
static constexpr int A_BYTES = 128 * 128;        // 16 KB
static constexpr int B_BYTES = 128 * 128;        // 16 KB
static constexpr int BUF_B = A_BYTES + B_BYTES;  // 32 KB
static constexpr int GEMM_SMEM = 3 * BUF_B;      // 96 KB

__global__ __launch_bounds__(GT, 2) void gemm_kernel() {
    extern __shared__ char smem[];
    const uint32_t sb = smem_to_u32(smem);
    const int tid = threadIdx.x, wid = tid >> 5, lid = tid & 31;
    const int b = blockIdx.z, m0 = blockIdx.y * 128, n0 = blockIdx.x * 128;
    const int warp_m = wid & 1, warp_n = wid >> 1;   // 2m x 2n warps, 64x64 each

    const __half* Ap = g_Ah + (size_t)b * PTOT * 256;
    const __half* Bp = g_Bh + (size_t)b * QPAD * 256;

    float acc[4][8][4];
#pragma unroll
    for (int i = 0; i < 4; i++)
#pragma unroll
        for (int j = 0; j < 8; j++)
#pragma unroll
            for (int k = 0; k < 4; k++) acc[i][j][k] = 0.f;

    // async load of chunk c (k-offset c*64) into buffer `buf` (0..2)
    auto issue_loads = [&](int c, int buf) {
        int k_off = c * 64;
        uint32_t aB = sb + buf * BUF_B;
        uint32_t bB = aB + A_BYTES;
#pragma unroll
        for (int i = 0; i < 16; i++) {
            int idx = tid + i * GT;               // 0..2047
            bool isB = idx >= 1024;
            int j = isB ? idx - 1024 : idx;
            int row = j >> 3, c16 = j & 7;
            const __half* src = isB
                ? Bp + (size_t)(n0 + row) * 256 + k_off + c16 * 8
                : Ap + (size_t)(m0 + row) * 256 + k_off + c16 * 8;
            uint32_t dst = (isB ? bB : aB) + SWZ((uint32_t)(row * 128 + c16 * 16));
            cp_async16(dst, src);
        }
        asm volatile("cp.async.commit_group;" ::: "memory");
    };

    issue_loads(0, 0);
    issue_loads(1, 1);

    const int a_row = warp_m * 64 + (lid & 15);
    const int a_kb  = (lid >> 4) * 16;
    const int b_row = warp_n * 64 + ((lid >> 4) & 1) * 8 + (lid & 7);
    const int b_kb  = ((lid >> 3) & 1) * 16;

    for (int c = 0; c < 4; c++) {
        if (c < 3) asm volatile("cp.async.wait_group 1;" ::: "memory");
        else       asm volatile("cp.async.wait_group 0;" ::: "memory");
        __syncthreads();              // chunk c resident; all warps left chunk c-1
        if (c < 2) issue_loads(c + 2, (c + 2) % 3);

        uint32_t aB = sb + (c % 3) * BUF_B;
        uint32_t bB = aB + A_BYTES;

#pragma unroll
        for (int ks = 0; ks < 4; ks++) {
            uint32_t af[4][4];
            uint32_t aAddr = aB + SWZ((uint32_t)(a_row * 128 + ks * 32 + a_kb));
#pragma unroll
            for (int mb = 0; mb < 4; mb++) ldsm_x4(af[mb], aAddr + mb * 2048);

            uint32_t bf[4][4];
            uint32_t bAddr = bB + SWZ((uint32_t)(b_row * 128 + ks * 32 + b_kb));
#pragma unroll
            for (int p = 0; p < 4; p++) ldsm_x4(bf[p], bAddr + p * 2048);

#pragma unroll
            for (int mb = 0; mb < 4; mb++)
#pragma unroll
                for (int nb = 0; nb < 8; nb++)
                    mma16816(acc[mb][nb], af[mb],
                             bf[nb >> 1][(nb & 1) * 2], bf[nb >> 1][(nb & 1) * 2 + 1]);
        }
    }

    // epilogue: scale 1/16, convert to fp16, store
    const float scale = 0.0625f;
    const int rbase = m0 + warp_m * 64 + (lid >> 2);
    const int cbase = n0 + warp_n * 64 + (lid & 3) * 2;
#pragma unroll
    for (int mb = 0; mb < 4; mb++) {
#pragma unroll
        for (int nb = 0; nb < 8; nb++) {
            int q = cbase + nb * 8;
            if (q < QTOT) {
                int r0 = rbase + mb * 16;
                __half* c0p = g_corrh + ((size_t)b * PTOT + r0) * QTOT + q;
                __half* c1p = c0p + (size_t)8 * QTOT;
                *(__half2*)c0p = __floats2half2_rn(acc[mb][nb][0] * scale,
                                                   acc[mb][nb][1] * scale);
                *(__half2*)c1p = __floats2half2_rn(acc[mb][nb][2] * scale,
                                                   acc[mb][nb][3] * scale);
            }
        }
    }
}

// ---------------------------------------------------------------------------
// Kernel 4: sampler, warp-per-query, fp16 corr, all-level prefetch. grid 4096.
// ---------------------------------------------------------------------------
__global__ __launch_bounds__(128) void sample_kernel(const float* __restrict__ coords,
                                                     float* __restrict__ out) {
    const int warp = threadIdx.x >> 5;
    const int lane = threadIdx.x & 31;
    const int qid = blockIdx.x * 4 + warp;      // (((b*8+n)*64+h)*64+w)
    const int w = qid & 63;
    const int h = (qid >> 6) & 63;
    const int n = (qid >> 12) & 7;
    const int b = qid >> 15;

    __shared__ float patch[4][4][10][16];       // [warp][lvl][row][col]

    const float cx = coords[((((size_t)b * NN + n) * 2 + 0) * HH + h) * WW + w];
    const float cy = coords[((((size_t)b * NN + n) * 2 + 1) * HH + h) * WW + w];

    const int p = h * WW + w;
    const __half* corrRow = g_corrh + ((size_t)b * PTOT + p) * QTOT;
    float* outBase = out + (size_t)qid * 324;

    const int   lvl_off[4] = {0, 4096, 5120, 5376};
    const int   wl[4]      = {64, 32, 16, 8};
    const float inv[4]     = {1.f, 0.5f, 0.25f, 0.125f};

    float cxs_[4], cys_[4], wm1_[4];
    int   xs4_[4], yst_[4];

    // Phase 1: issue ALL levels' patch loads (independent -> high MLP)
#pragma unroll
    for (int lvl = 0; lvl < 4; lvl++) {
        const int   w2  = wl[lvl];
        const float wm1 = (float)(w2 - 1);
        const float cxs = cx * inv[lvl];
        const float cys = cy * inv[lvl];
        const float ylo = fminf(fmaxf(cys - 4.f, 0.f), wm1);
        const float yhi = fminf(fmaxf(cys + 4.f, 0.f), wm1);
        const float xlo = fminf(fmaxf(cxs - 4.f, 0.f), wm1);
        const int xstart = (int)floorf(xlo);
        const int ystart = (int)floorf(ylo);
        const int yend   = min((int)floorf(yhi) + 1, w2 - 1);
        const int xs4    = xstart & ~3;

        cxs_[lvl] = cxs; cys_[lvl] = cys; wm1_[lvl] = wm1;
        xs4_[lvl] = xs4; yst_[lvl] = ystart;

        const __half* lbase = corrRow + lvl_off[lvl];
#pragma unroll
        for (int s = 0; s < 2; s++) {
            int slot = lane + s * 32;
            if (slot < 40) {
                int r = slot >> 2, cb = slot & 3;
                int col = xs4 + cb * 4;
                if (r <= yend - ystart && col < w2) {
                    uint2 v = *(const uint2*)(lbase + (ystart + r) * w2 + col);
                    float2 f0 = __half22float2(*(__half2*)&v.x);
                    float2 f1 = __half22float2(*(__half2*)&v.y);
                    patch[warp][lvl][r][cb * 4 + 0] = f0.x;
                    patch[warp][lvl][r][cb * 4 + 1] = f0.y;
                    patch[warp][lvl][r][cb * 4 + 2] = f1.x;
                    patch[warp][lvl][r][cb * 4 + 3] = f1.y;
                }
            }
        }
    }
    __syncwarp();

    // Phase 2: bilinear combine for all levels
#pragma unroll
    for (int lvl = 0; lvl < 4; lvl++) {
        const int   w2  = wl[lvl];
        const float wm1 = wm1_[lvl];
        const float cxs = cxs_[lvl];
        const float cys = cys_[lvl];
        const int   xs4 = xs4_[lvl];
        const int   yst = yst_[lvl];
        float (*pp)[16] = patch[warp][lvl];

#pragma unroll
        for (int s = 0; s < 3; s++) {
            int t = lane + s * 32;
            if (t < 81) {
                const int ix = t / 9;
                const int iy = t - ix * 9;
                float x = fminf(fmaxf(cxs + (float)(ix - 4), 0.f), wm1);
                float y = fminf(fmaxf(cys + (float)(iy - 4), 0.f), wm1);
                float x0f = floorf(x), y0f = floorf(y);
                float fx = x - x0f, fy = y - y0f;
                int x0 = (int)x0f;
                int y0 = (int)y0f;
                int x1 = min(x0 + 1, w2 - 1) - xs4;
                int y1 = min(y0 + 1, w2 - 1) - yst;
                x0 -= xs4;
                y0 -= yst;

                float v00 = pp[y0][x0], v01 = pp[y0][x1];
                float v10 = pp[y1][x0], v11 = pp[y1][x1];
                float v = v00 * (1.f - fy) * (1.f - fx)
                        + v01 * (1.f - fy) * fx
                        + v10 * fy * (1.f - fx)
                        + v11 * fy * fx;
                outBase[lvl * 81 + t] = v;
            }
        }
    }
}

// ---------------------------------------------------------------------------
// Launch
// ---------------------------------------------------------------------------
extern "C" void kernel_launch(void* const* d_in, const int* in_sizes, int n_in,
                              void* d_out, int out_size) {
    const float* f1     = (const float*)d_in[0];
    const float* f2     = (const float*)d_in[1];
    const float* coords = (const float*)d_in[2];
    float* out          = (float*)d_out;

    pool_kernel<<<dim3(Cc, Bb), 256>>>(f2);
    aprep_kernel<<<dim3(PTOT / 32, Cc / 32, Bb), dim3(32, 8)>>>(f1);
    bprep_kernel<<<dim3(QPAD / 32, Cc / 32, Bb), dim3(32, 8)>>>();

    cudaFuncSetAttribute(gemm_kernel, cudaFuncAttributeMaxDynamicSharedMemorySize, GEMM_SMEM);
    gemm_kernel<<<dim3(QPAD / 128, PTOT / 128, Bb), GT, GEMM_SMEM>>>();

    sample_kernel<<<Bb * NN * HH * WW / 4, 128>>>(coords, out);
}

// round 10
// speedup vs baseline: 1.0252x; 1.0252x over previous
#include <cuda_runtime.h>
#include <cuda_fp16.h>
#include <cstdint>

// ---------------------------------------------------------------------------
// CorrBlock: pooled-fmap2 fp16 HMMA GEMM (1-pass: Ahi*Bhi) + warp sampler.
// corr = (1/16) * f1^T f2cat ≈ (1/16)(Ahi*Bhi), fp32 acc, fp16 store.
// Round 10: GEMM = round-8 config (measured best 73.5us).
//           Pool writes fp16 directly (no fp32 f2cat round-trip).
//           Sampler: 256-thr block = 8 n-heads of one (b,h,w) -> corr-row reuse.
// ---------------------------------------------------------------------------

#define Bb 2
#define Cc 256
#define HH 64
#define WW 64
#define NN 8
#define QTOT 5440
#define QPAD 5632      // 44 N-tiles of 128
#define PTOT 4096      // H*W

// Scratch (no cudaMalloc allowed)
__device__ __half g_Bt[(size_t)Bb * Cc * QTOT];           // 5.6 MB  [b][c][q] fp16
__device__ __half g_Ah[(size_t)Bb * PTOT * 256];          // 4.2 MB  [m][hi]
__device__ __half g_Bh[(size_t)Bb * QPAD * 256];          // 5.7 MB  [q][hi]
__device__ __half g_corrh[(size_t)Bb * PTOT * QTOT];      // 89 MB   fp16 corr

#define SWZ(o) ((o) ^ (((o) >> 3) & 0x70))

__device__ __forceinline__ uint32_t smem_to_u32(const void* p) {
    uint32_t a;
    asm("{ .reg .u64 t; cvta.to.shared.u64 t, %1; cvt.u32.u64 %0, t; }" : "=r"(a) : "l"(p));
    return a;
}
__device__ __forceinline__ void cp_async16(uint32_t dst, const void* src) {
    asm volatile("cp.async.cg.shared.global [%0], [%1], 16;" :: "r"(dst), "l"(src));
}
__device__ __forceinline__ void ldsm_x4(uint32_t* r, uint32_t addr) {
    asm volatile("ldmatrix.sync.aligned.m8n8.x4.shared.b16 {%0,%1,%2,%3}, [%4];"
                 : "=r"(r[0]), "=r"(r[1]), "=r"(r[2]), "=r"(r[3]) : "r"(addr));
}
__device__ __forceinline__ void mma16816(float* d, const uint32_t* a, uint32_t b0, uint32_t b1) {
    asm volatile("mma.sync.aligned.m16n8k16.row.col.f32.f16.f16.f32 "
                 "{%0,%1,%2,%3}, {%4,%5,%6,%7}, {%8,%9}, {%0,%1,%2,%3};"
                 : "+f"(d[0]), "+f"(d[1]), "+f"(d[2]), "+f"(d[3])
                 : "r"(a[0]), "r"(a[1]), "r"(a[2]), "r"(a[3]), "r"(b0), "r"(b1));
}

// ---------------------------------------------------------------------------
// Kernel 1: pool fmap2 into 4 levels, write fp16 [b][c][q]. grid (C, B), 256t.
// ---------------------------------------------------------------------------
__global__ __launch_bounds__(256) void pool_kernel(const float* __restrict__ f2) {
    int c = blockIdx.x, b = blockIdx.y;
    const float* in = f2 + ((size_t)b * Cc + c) * (HH * WW);
    __half* outp = g_Bt + ((size_t)b * Cc + c) * QTOT;
    __shared__ float s0[4096];
    __shared__ float s1[1024];
    __shared__ float s2[256];
    int tid = threadIdx.x;
    for (int i = tid; i < 1024; i += 256) {
        float4 v = ((const float4*)in)[i];
        ((float4*)s0)[i] = v;
        __half2 h0 = __floats2half2_rn(v.x, v.y);
        __half2 h1 = __floats2half2_rn(v.z, v.w);
        ((__half2*)outp)[2 * i]     = h0;
        ((__half2*)outp)[2 * i + 1] = h1;
    }
    __syncthreads();
    for (int o = tid; o < 1024; o += 256) {
        int y = o >> 5, x = o & 31;
        float v = 0.25f * (s0[(2*y)*64 + 2*x] + s0[(2*y)*64 + 2*x + 1]
                         + s0[(2*y+1)*64 + 2*x] + s0[(2*y+1)*64 + 2*x + 1]);
        s1[o] = v; outp[4096 + o] = __float2half_rn(v);
    }
    __syncthreads();
    if (tid < 256) {
        int y = tid >> 4, x = tid & 15;
        float v = 0.25f * (s1[(2*y)*32 + 2*x] + s1[(2*y)*32 + 2*x + 1]
                         + s1[(2*y+1)*32 + 2*x] + s1[(2*y+1)*32 + 2*x + 1]);
        s2[tid] = v; outp[5120 + tid] = __float2half_rn(v);
    }
    __syncthreads();
    if (tid < 64) {
        int y = tid >> 3, x = tid & 7;
        float v = 0.25f * (s2[(2*y)*16 + 2*x] + s2[(2*y)*16 + 2*x + 1]
                         + s2[(2*y+1)*16 + 2*x] + s2[(2*y+1)*16 + 2*x + 1]);
        outp[5376 + tid] = __float2half_rn(v);
    }
}

// ---------------------------------------------------------------------------
// Kernel 2a: transpose f1 [b][c][p] -> fp16 hi [b][p][256]
// ---------------------------------------------------------------------------
__global__ __launch_bounds__(256) void aprep_kernel(const float* __restrict__ f1) {
    __shared__ float tile[32][33];
    int b = blockIdx.z, p0 = blockIdx.x * 32, c0 = blockIdx.y * 32;
    int tx = threadIdx.x, ty = threadIdx.y;
#pragma unroll
    for (int k = 0; k < 4; k++) {
        int c = c0 + ty + 8 * k;
        tile[ty + 8 * k][tx] = f1[((size_t)b * Cc + c) * PTOT + p0 + tx];
    }
    __syncthreads();
#pragma unroll
    for (int k = 0; k < 4; k++) {
        int p = p0 + ty + 8 * k, c = c0 + tx;
        g_Ah[((size_t)b * PTOT + p) * 256 + c] = __float2half_rn(tile[tx][ty + 8 * k]);
    }
}

// ---------------------------------------------------------------------------
// Kernel 2b: transpose g_Bt [b][c][q] fp16 -> [b][q][256], pad q>=5440
// ---------------------------------------------------------------------------
__global__ __launch_bounds__(256) void bprep_kernel() {
    __shared__ __half tile[32][34];
    int b = blockIdx.z, q0 = blockIdx.x * 32, c0 = blockIdx.y * 32;
    int tx = threadIdx.x, ty = threadIdx.y;
#pragma unroll
    for (int k = 0; k < 4; k++) {
        int c = c0 + ty + 8 * k, q = q0 + tx;
        tile[ty + 8 * k][tx] = (q < QTOT) ? g_Bt[((size_t)b * Cc + c) * QTOT + q]
                                          : __half(0.f);
    }
    __syncthreads();
#pragma unroll
    for (int k = 0; k < 4; k++) {
        int q = q0 + ty + 8 * k, c = c0 + tx;
        g_Bh[((size_t)b * QPAD + q) * 256 + c] = tile[tx][ty + 8 * k];
    }
}

// ---------------------------------------------------------------------------
// Kernel 3: HMMA GEMM (round-8 config). CTA 128(M) x 128(N), BK=64, 4 chunks,
// 256 threads / 8 warps (warp tile 32x64), 3-stage cp.async, 2 CTAs/SM.
// grid (44, 32, 2).
// ---------------------------------------------------------------------------
#define GT 256
static constexpr int A_BYTES = 128 * 128;        // 16 KB
static constexpr int B_BYTES = 128 * 128;        // 16 KB
static constexpr int BUF_B = A_BYTES + B_BYTES;  // 32 KB
static constexpr int GEMM_SMEM = 3 * BUF_B;      // 96 KB

__global__ __launch_bounds__(GT, 2) void gemm_kernel() {
    extern __shared__ char smem[];
    const uint32_t sb = smem_to_u32(smem);
    const int tid = threadIdx.x, wid = tid >> 5, lid = tid & 31;
    const int b = blockIdx.z, m0 = blockIdx.y * 128, n0 = blockIdx.x * 128;
    const int warp_m = wid & 3, warp_n = wid >> 2;   // 4m x 2n warps, 32x64 each

    const __half* Ap = g_Ah + (size_t)b * PTOT * 256;
    const __half* Bp = g_Bh + (size_t)b * QPAD * 256;

    float acc[2][8][4];
#pragma unroll
    for (int i = 0; i < 2; i++)
#pragma unroll
        for (int j = 0; j < 8; j++)
#pragma unroll
            for (int k = 0; k < 4; k++) acc[i][j][k] = 0.f;

    auto issue_loads = [&](int c, int buf) {
        int k_off = c * 64;
        uint32_t aB = sb + buf * BUF_B;
        uint32_t bB = aB + A_BYTES;
#pragma unroll
        for (int i = 0; i < 8; i++) {
            int idx = tid + i * GT;               // 0..2047
            bool isB = idx >= 1024;
            int j = isB ? idx - 1024 : idx;
            int row = j >> 3, c16 = j & 7;
            const __half* src = isB
                ? Bp + (size_t)(n0 + row) * 256 + k_off + c16 * 8
                : Ap + (size_t)(m0 + row) * 256 + k_off + c16 * 8;
            uint32_t dst = (isB ? bB : aB) + SWZ((uint32_t)(row * 128 + c16 * 16));
            cp_async16(dst, src);
        }
        asm volatile("cp.async.commit_group;" ::: "memory");
    };

    issue_loads(0, 0);
    issue_loads(1, 1);

    const int a_row = warp_m * 32 + (lid & 15);
    const int a_kb  = (lid >> 4) * 16;
    const int b_row = warp_n * 64 + ((lid >> 4) & 1) * 8 + (lid & 7);
    const int b_kb  = ((lid >> 3) & 1) * 16;

    for (int c = 0; c < 4; c++) {
        if (c < 3) asm volatile("cp.async.wait_group 1;" ::: "memory");
        else       asm volatile("cp.async.wait_group 0;" ::: "memory");
        __syncthreads();
        if (c < 2) issue_loads(c + 2, (c + 2) % 3);

        uint32_t aB = sb + (c % 3) * BUF_B;
        uint32_t bB = aB + A_BYTES;

#pragma unroll
        for (int ks = 0; ks < 4; ks++) {
            uint32_t af[2][4];
            uint32_t aAddr = aB + SWZ((uint32_t)(a_row * 128 + ks * 32 + a_kb));
            ldsm_x4(af[0], aAddr);
            ldsm_x4(af[1], aAddr + 2048);        // +16 rows

            uint32_t bf[4][4];
            uint32_t bAddr = bB + SWZ((uint32_t)(b_row * 128 + ks * 32 + b_kb));
#pragma unroll
            for (int p = 0; p < 4; p++) ldsm_x4(bf[p], bAddr + p * 2048);

#pragma unroll
            for (int mb = 0; mb < 2; mb++)
#pragma unroll
                for (int nb = 0; nb < 8; nb++)
                    mma16816(acc[mb][nb], af[mb],
                             bf[nb >> 1][(nb & 1) * 2], bf[nb >> 1][(nb & 1) * 2 + 1]);
        }
    }

    const float scale = 0.0625f;
    const int rbase = m0 + warp_m * 32 + (lid >> 2);
    const int cbase = n0 + warp_n * 64 + (lid & 3) * 2;
#pragma unroll
    for (int mb = 0; mb < 2; mb++) {
#pragma unroll
        for (int nb = 0; nb < 8; nb++) {
            int q = cbase + nb * 8;
            if (q < QTOT) {
                int r0 = rbase + mb * 16;
                __half* c0p = g_corrh + ((size_t)b * PTOT + r0) * QTOT + q;
                __half* c1p = c0p + (size_t)8 * QTOT;
                *(__half2*)c0p = __floats2half2_rn(acc[mb][nb][0] * scale,
                                                   acc[mb][nb][1] * scale);
                *(__half2*)c1p = __floats2half2_rn(acc[mb][nb][2] * scale,
                                                   acc[mb][nb][3] * scale);
            }
        }
    }
}

// ---------------------------------------------------------------------------
// Kernel 4: sampler. One 256-thr block = 8 warps = the 8 n-heads of one
// (b,h,w) query point -> all warps share the same corr row (L1/L2 reuse).
// grid 8192.
// ---------------------------------------------------------------------------
__global__ __launch_bounds__(256) void sample_kernel(const float* __restrict__ coords,
                                                     float* __restrict__ out) {
    const int warp = threadIdx.x >> 5;          // = n (0..7)
    const int lane = threadIdx.x & 31;
    const int bhw = blockIdx.x;                  // b*4096 + h*64 + w
    const int b = bhw >> 12;
    const int hw = bhw & 4095;
    const int h = hw >> 6;
    const int w = hw & 63;
    const int n = warp;
    const int qid = ((b * NN + n) << 12) | hw;

    __shared__ float patch[8][4][10][16];       // [warp][lvl][row][col]

    const float cx = coords[((((size_t)b * NN + n) * 2 + 0) * HH + h) * WW + w];
    const float cy = coords[((((size_t)b * NN + n) * 2 + 1) * HH + h) * WW + w];

    const int p = hw;                            // h*64+w
    const __half* corrRow = g_corrh + ((size_t)b * PTOT + p) * QTOT;
    float* outBase = out + (size_t)qid * 324;

    const int   lvl_off[4] = {0, 4096, 5120, 5376};
    const int   wl[4]      = {64, 32, 16, 8};
    const float inv[4]     = {1.f, 0.5f, 0.25f, 0.125f};

    float cxs_[4], cys_[4], wm1_[4];
    int   xs4_[4], yst_[4];

    // Phase 1: issue all 4 levels' patch loads (high MLP, shared row)
#pragma unroll
    for (int lvl = 0; lvl < 4; lvl++) {
        const int   w2  = wl[lvl];
        const float wm1 = (float)(w2 - 1);
        const float cxs = cx * inv[lvl];
        const float cys = cy * inv[lvl];
        const float ylo = fminf(fmaxf(cys - 4.f, 0.f), wm1);
        const float yhi = fminf(fmaxf(cys + 4.f, 0.f), wm1);
        const float xlo = fminf(fmaxf(cxs - 4.f, 0.f), wm1);
        const int xstart = (int)floorf(xlo);
        const int ystart = (int)floorf(ylo);
        const int yend   = min((int)floorf(yhi) + 1, w2 - 1);
        const int xs4    = xstart & ~3;

        cxs_[lvl] = cxs; cys_[lvl] = cys; wm1_[lvl] = wm1;
        xs4_[lvl] = xs4; yst_[lvl] = ystart;

        const __half* lbase = corrRow + lvl_off[lvl];
#pragma unroll
        for (int s = 0; s < 2; s++) {
            int slot = lane + s * 32;
            if (slot < 40) {
                int r = slot >> 2, cb = slot & 3;
                int col = xs4 + cb * 4;
                if (r <= yend - ystart && col < w2) {
                    uint2 v = *(const uint2*)(lbase + (ystart + r) * w2 + col);
                    float2 f0 = __half22float2(*(__half2*)&v.x);
                    float2 f1 = __half22float2(*(__half2*)&v.y);
                    patch[warp][lvl][r][cb * 4 + 0] = f0.x;
                    patch[warp][lvl][r][cb * 4 + 1] = f0.y;
                    patch[warp][lvl][r][cb * 4 + 2] = f1.x;
                    patch[warp][lvl][r][cb * 4 + 3] = f1.y;
                }
            }
        }
    }
    __syncwarp();

    // Phase 2: bilinear combine
#pragma unroll
    for (int lvl = 0; lvl < 4; lvl++) {
        const int   w2  = wl[lvl];
        const float wm1 = wm1_[lvl];
        const float cxs = cxs_[lvl];
        const float cys = cys_[lvl];
        const int   xs4 = xs4_[lvl];
        const int   yst = yst_[lvl];
        float (*pp)[16] = patch[warp][lvl];

#pragma unroll
        for (int s = 0; s < 3; s++) {
            int t = lane + s * 32;
            if (t < 81) {
                const int ix = t / 9;
                const int iy = t - ix * 9;
                float x = fminf(fmaxf(cxs + (float)(ix - 4), 0.f), wm1);
                float y = fminf(fmaxf(cys + (float)(iy - 4), 0.f), wm1);
                float x0f = floorf(x), y0f = floorf(y);
                float fx = x - x0f, fy = y - y0f;
                int x0 = (int)x0f;
                int y0 = (int)y0f;
                int x1 = min(x0 + 1, w2 - 1) - xs4;
                int y1 = min(y0 + 1, w2 - 1) - yst;
                x0 -= xs4;
                y0 -= yst;

                float v00 = pp[y0][x0], v01 = pp[y0][x1];
                float v10 = pp[y1][x0], v11 = pp[y1][x1];
                float v = v00 * (1.f - fy) * (1.f - fx)
                        + v01 * (1.f - fy) * fx
                        + v10 * fy * (1.f - fx)
                        + v11 * fy * fx;
                outBase[lvl * 81 + t] = v;
            }
        }
    }
}

// ---------------------------------------------------------------------------
// Launch
// ---------------------------------------------------------------------------
extern "C" void kernel_launch(void* const* d_in, const int* in_sizes, int n_in,
                              void* d_out, int out_size) {
    const float* f1     = (const float*)d_in[0];
    const float* f2     = (const float*)d_in[1];
    const float* coords = (const float*)d_in[2];
    float* out          = (float*)d_out;

    pool_kernel<<<dim3(Cc, Bb), 256>>>(f2);
    aprep_kernel<<<dim3(PTOT / 32, Cc / 32, Bb), dim3(32, 8)>>>(f1);
    bprep_kernel<<<dim3(QPAD / 32, Cc / 32, Bb), dim3(32, 8)>>>();

    cudaFuncSetAttribute(gemm_kernel, cudaFuncAttributeMaxDynamicSharedMemorySize, GEMM_SMEM);
    gemm_kernel<<<dim3(QPAD / 128, PTOT / 128, Bb), GT, GEMM_SMEM>>>();

    sample_kernel<<<Bb * HH * WW, 256>>>(coords, out);
}

// round 11
// speedup vs baseline: 1.0835x; 1.0569x over previous
#include <cuda_runtime.h>
#include <cuda_fp16.h>
#include <cstdint>

// ---------------------------------------------------------------------------
// CorrBlock: pooled-fmap2 fp16 HMMA GEMM (1-pass: Ahi*Bhi) + warp sampler.
// Round 11: sampler patch rows padded 16->20 floats (kills LDS bank conflicts,
//           bank = (20*y0+x0)&31 spreads rows; float4 stores stay aligned);
//           pool + aprep fused into one kernel (independent -> concurrent).
// GEMM unchanged (round-8 measured optimum, 73.3us).
// ---------------------------------------------------------------------------

#define Bb 2
#define Cc 256
#define HH 64
#define WW 64
#define NN 8
#define QTOT 5440
#define QPAD 5632      // 44 N-tiles of 128
#define PTOT 4096      // H*W

// Scratch (no cudaMalloc allowed)
__device__ __half g_Bt[(size_t)Bb * Cc * QTOT];           // 5.6 MB  [b][c][q] fp16
__device__ __half g_Ah[(size_t)Bb * PTOT * 256];          // 4.2 MB  [m][hi]
__device__ __half g_Bh[(size_t)Bb * QPAD * 256];          // 5.7 MB  [q][hi]
__device__ __half g_corrh[(size_t)Bb * PTOT * QTOT];      // 89 MB   fp16 corr

#define SWZ(o) ((o) ^ (((o) >> 3) & 0x70))

__device__ __forceinline__ uint32_t smem_to_u32(const void* p) {
    uint32_t a;
    asm("{ .reg .u64 t; cvta.to.shared.u64 t, %1; cvt.u32.u64 %0, t; }" : "=r"(a) : "l"(p));
    return a;
}
__device__ __forceinline__ void cp_async16(uint32_t dst, const void* src) {
    asm volatile("cp.async.cg.shared.global [%0], [%1], 16;" :: "r"(dst), "l"(src));
}
__device__ __forceinline__ void ldsm_x4(uint32_t* r, uint32_t addr) {
    asm volatile("ldmatrix.sync.aligned.m8n8.x4.shared.b16 {%0,%1,%2,%3}, [%4];"
                 : "=r"(r[0]), "=r"(r[1]), "=r"(r[2]), "=r"(r[3]) : "r"(addr));
}
__device__ __forceinline__ void mma16816(float* d, const uint32_t* a, uint32_t b0, uint32_t b1) {
    asm volatile("mma.sync.aligned.m16n8k16.row.col.f32.f16.f16.f32 "
                 "{%0,%1,%2,%3}, {%4,%5,%6,%7}, {%8,%9}, {%0,%1,%2,%3};"
                 : "+f"(d[0]), "+f"(d[1]), "+f"(d[2]), "+f"(d[3])
                 : "r"(a[0]), "r"(a[1]), "r"(a[2]), "r"(a[3]), "r"(b0), "r"(b1));
}

// ---------------------------------------------------------------------------
// Kernel 1: fused prep. Blocks [0,512): pool fmap2 -> fp16 g_Bt.
//           Blocks [512,2560): transpose f1 -> fp16 g_Ah. 256 threads.
// ---------------------------------------------------------------------------
__global__ __launch_bounds__(256) void prep_kernel(const float* __restrict__ f2,
                                                   const float* __restrict__ f1) {
    __shared__ float s0[4096];
    __shared__ float s1[1024];
    __shared__ float s2[256];
    __shared__ float tile[32][33];
    const int blk = blockIdx.x;
    const int tid = threadIdx.x;

    if (blk < 512) {
        // ---- pool: (b, c) = (blk>>8, blk&255) ----
        int c = blk & 255, b = blk >> 8;
        const float* in = f2 + ((size_t)b * Cc + c) * (HH * WW);
        __half* outp = g_Bt + ((size_t)b * Cc + c) * QTOT;
        for (int i = tid; i < 1024; i += 256) {
            float4 v = ((const float4*)in)[i];
            ((float4*)s0)[i] = v;
            ((__half2*)outp)[2 * i]     = __floats2half2_rn(v.x, v.y);
            ((__half2*)outp)[2 * i + 1] = __floats2half2_rn(v.z, v.w);
        }
        __syncthreads();
        for (int o = tid; o < 1024; o += 256) {
            int y = o >> 5, x = o & 31;
            float v = 0.25f * (s0[(2*y)*64 + 2*x] + s0[(2*y)*64 + 2*x + 1]
                             + s0[(2*y+1)*64 + 2*x] + s0[(2*y+1)*64 + 2*x + 1]);
            s1[o] = v; outp[4096 + o] = __float2half_rn(v);
        }
        __syncthreads();
        {
            int y = tid >> 4, x = tid & 15;
            float v = 0.25f * (s1[(2*y)*32 + 2*x] + s1[(2*y)*32 + 2*x + 1]
                             + s1[(2*y+1)*32 + 2*x] + s1[(2*y+1)*32 + 2*x + 1]);
            s2[tid] = v; outp[5120 + tid] = __float2half_rn(v);
        }
        __syncthreads();
        if (tid < 64) {
            int y = tid >> 3, x = tid & 7;
            float v = 0.25f * (s2[(2*y)*16 + 2*x] + s2[(2*y)*16 + 2*x + 1]
                             + s2[(2*y+1)*16 + 2*x] + s2[(2*y+1)*16 + 2*x + 1]);
            outp[5376 + tid] = __float2half_rn(v);
        }
    } else {
        // ---- aprep: blk2 in [0,2048): p0=(blk2&127)*32, c0=((blk2>>7)&7)*32, b=blk2>>10
        int blk2 = blk - 512;
        int p0 = (blk2 & 127) * 32;
        int c0 = ((blk2 >> 7) & 7) * 32;
        int b  = blk2 >> 10;
        int tx = tid & 31, ty = tid >> 5;
#pragma unroll
        for (int k = 0; k < 4; k++) {
            int c = c0 + ty + 8 * k;
            tile[ty + 8 * k][tx] = f1[((size_t)b * Cc + c) * PTOT + p0 + tx];
        }
        __syncthreads();
#pragma unroll
        for (int k = 0; k < 4; k++) {
            int p = p0 + ty + 8 * k, c = c0 + tx;
            g_Ah[((size_t)b * PTOT + p) * 256 + c] = __float2half_rn(tile[tx][ty + 8 * k]);
        }
    }
}

// ---------------------------------------------------------------------------
// Kernel 2: transpose g_Bt [b][c][q] fp16 -> [b][q][256], pad q>=5440
// ---------------------------------------------------------------------------
__global__ __launch_bounds__(256) void bprep_kernel() {
    __shared__ __half tile[32][34];
    int b = blockIdx.z, q0 = blockIdx.x * 32, c0 = blockIdx.y * 32;
    int tx = threadIdx.x, ty = threadIdx.y;
#pragma unroll
    for (int k = 0; k < 4; k++) {
        int c = c0 + ty + 8 * k, q = q0 + tx;
        tile[ty + 8 * k][tx] = (q < QTOT) ? g_Bt[((size_t)b * Cc + c) * QTOT + q]
                                          : __half(0.f);
    }
    __syncthreads();
#pragma unroll
    for (int k = 0; k < 4; k++) {
        int q = q0 + ty + 8 * k, c = c0 + tx;
        g_Bh[((size_t)b * QPAD + q) * 256 + c] = tile[tx][ty + 8 * k];
    }
}

// ---------------------------------------------------------------------------
// Kernel 3: HMMA GEMM (round-8 config, unchanged). CTA 128x128, BK=64, 4 chunks,
// 256 threads / 8 warps (warp tile 32x64), 3-stage cp.async, 2 CTAs/SM.
// grid (44, 32, 2).
// ---------------------------------------------------------------------------
#define GT 256
static constexpr int A_BYTES = 128 * 128;        // 16 KB
static constexpr int B_BYTES = 128 * 128;        // 16 KB
static constexpr int BUF_B = A_BYTES + B_BYTES;  // 32 KB
static constexpr int GEMM_SMEM = 3 * BUF_B;      // 96 KB

__global__ __launch_bounds__(GT, 2) void gemm_kernel() {
    extern __shared__ char smem[];
    const uint32_t sb = smem_to_u32(smem);
    const int tid = threadIdx.x, wid = tid >> 5, lid = tid & 31;
    const int b = blockIdx.z, m0 = blockIdx.y * 128, n0 = blockIdx.x * 128;
    const int warp_m = wid & 3, warp_n = wid >> 2;   // 4m x 2n warps, 32x64 each

    const __half* Ap = g_Ah + (size_t)b * PTOT * 256;
    const __half* Bp = g_Bh + (size_t)b * QPAD * 256;

    float acc[2][8][4];
#pragma unroll
    for (int i = 0; i < 2; i++)
#pragma unroll
        for (int j = 0; j < 8; j++)
#pragma unroll
            for (int k = 0; k < 4; k++) acc[i][j][k] = 0.f;

    auto issue_loads = [&](int c, int buf) {
        int k_off = c * 64;
        uint32_t aB = sb + buf * BUF_B;
        uint32_t bB = aB + A_BYTES;
#pragma unroll
        for (int i = 0; i < 8; i++) {
            int idx = tid + i * GT;               // 0..2047
            bool isB = idx >= 1024;
            int j = isB ? idx - 1024 : idx;
            int row = j >> 3, c16 = j & 7;
            const __half* src = isB
                ? Bp + (size_t)(n0 + row) * 256 + k_off + c16 * 8
                : Ap + (size_t)(m0 + row) * 256 + k_off + c16 * 8;
            uint32_t dst = (isB ? bB : aB) + SWZ((uint32_t)(row * 128 + c16 * 16));
            cp_async16(dst, src);
        }
        asm volatile("cp.async.commit_group;" ::: "memory");
    };

    issue_loads(0, 0);
    issue_loads(1, 1);

    const int a_row = warp_m * 32 + (lid & 15);
    const int a_kb  = (lid >> 4) * 16;
    const int b_row = warp_n * 64 + ((lid >> 4) & 1) * 8 + (lid & 7);
    const int b_kb  = ((lid >> 3) & 1) * 16;

    for (int c = 0; c < 4; c++) {
        if (c < 3) asm volatile("cp.async.wait_group 1;" ::: "memory");
        else       asm volatile("cp.async.wait_group 0;" ::: "memory");
        __syncthreads();
        if (c < 2) issue_loads(c + 2, (c + 2) % 3);

        uint32_t aB = sb + (c % 3) * BUF_B;
        uint32_t bB = aB + A_BYTES;

#pragma unroll
        for (int ks = 0; ks < 4; ks++) {
            uint32_t af[2][4];
            uint32_t aAddr = aB + SWZ((uint32_t)(a_row * 128 + ks * 32 + a_kb));
            ldsm_x4(af[0], aAddr);
            ldsm_x4(af[1], aAddr + 2048);        // +16 rows

            uint32_t bf[4][4];
            uint32_t bAddr = bB + SWZ((uint32_t)(b_row * 128 + ks * 32 + b_kb));
#pragma unroll
            for (int p = 0; p < 4; p++) ldsm_x4(bf[p], bAddr + p * 2048);

#pragma unroll
            for (int mb = 0; mb < 2; mb++)
#pragma unroll
                for (int nb = 0; nb < 8; nb++)
                    mma16816(acc[mb][nb], af[mb],
                             bf[nb >> 1][(nb & 1) * 2], bf[nb >> 1][(nb & 1) * 2 + 1]);
        }
    }

    const float scale = 0.0625f;
    const int rbase = m0 + warp_m * 32 + (lid >> 2);
    const int cbase = n0 + warp_n * 64 + (lid & 3) * 2;
#pragma unroll
    for (int mb = 0; mb < 2; mb++) {
#pragma unroll
        for (int nb = 0; nb < 8; nb++) {
            int q = cbase + nb * 8;
            if (q < QTOT) {
                int r0 = rbase + mb * 16;
                __half* c0p = g_corrh + ((size_t)b * PTOT + r0) * QTOT + q;
                __half* c1p = c0p + (size_t)8 * QTOT;
                *(__half2*)c0p = __floats2half2_rn(acc[mb][nb][0] * scale,
                                                   acc[mb][nb][1] * scale);
                *(__half2*)c1p = __floats2half2_rn(acc[mb][nb][2] * scale,
                                                   acc[mb][nb][3] * scale);
            }
        }
    }
}

// ---------------------------------------------------------------------------
// Kernel 4: sampler. One 256-thr block = 8 warps = 8 n-heads of one (b,h,w).
// Patch rows padded to 20 floats: bank = (20*y0 + x0) & 31 -> conflict-free-ish,
// float4 phase-1 stores stay 16B-aligned (20 % 4 == 0, 80B row stride).
// grid 8192.
// ---------------------------------------------------------------------------
#define PROW 20
__global__ __launch_bounds__(256) void sample_kernel(const float* __restrict__ coords,
                                                     float* __restrict__ out) {
    const int warp = threadIdx.x >> 5;          // = n (0..7)
    const int lane = threadIdx.x & 31;
    const int bhw = blockIdx.x;                  // b*4096 + h*64 + w
    const int b = bhw >> 12;
    const int hw = bhw & 4095;
    const int h = hw >> 6;
    const int w = hw & 63;
    const int n = warp;
    const int qid = ((b * NN + n) << 12) | hw;

    __shared__ float patch[8][4][10][PROW];     // [warp][lvl][row][col(padded)]

    const float cx = coords[((((size_t)b * NN + n) * 2 + 0) * HH + h) * WW + w];
    const float cy = coords[((((size_t)b * NN + n) * 2 + 1) * HH + h) * WW + w];

    const __half* corrRow = g_corrh + ((size_t)b * PTOT + hw) * QTOT;
    float* outBase = out + (size_t)qid * 324;

    const int   lvl_off[4] = {0, 4096, 5120, 5376};
    const int   wl[4]      = {64, 32, 16, 8};
    const float inv[4]     = {1.f, 0.5f, 0.25f, 0.125f};

    float cxs_[4], cys_[4], wm1_[4];
    int   xs4_[4], yst_[4];

    // Phase 1: issue all 4 levels' patch loads (high MLP, shared corr row)
#pragma unroll
    for (int lvl = 0; lvl < 4; lvl++) {
        const int   w2  = wl[lvl];
        const float wm1 = (float)(w2 - 1);
        const float cxs = cx * inv[lvl];
        const float cys = cy * inv[lvl];
        const float ylo = fminf(fmaxf(cys - 4.f, 0.f), wm1);
        const float yhi = fminf(fmaxf(cys + 4.f, 0.f), wm1);
        const float xlo = fminf(fmaxf(cxs - 4.f, 0.f), wm1);
        const int xstart = (int)floorf(xlo);
        const int ystart = (int)floorf(ylo);
        const int yend   = min((int)floorf(yhi) + 1, w2 - 1);
        const int xs4    = xstart & ~3;

        cxs_[lvl] = cxs; cys_[lvl] = cys; wm1_[lvl] = wm1;
        xs4_[lvl] = xs4; yst_[lvl] = ystart;

        const __half* lbase = corrRow + lvl_off[lvl];
#pragma unroll
        for (int s = 0; s < 2; s++) {
            int slot = lane + s * 32;
            if (slot < 40) {
                int r = slot >> 2, cb = slot & 3;
                int col = xs4 + cb * 4;
                if (r <= yend - ystart && col < w2) {
                    uint2 v = *(const uint2*)(lbase + (ystart + r) * w2 + col);
                    float2 f0 = __half22float2(*(__half2*)&v.x);
                    float2 f1 = __half22float2(*(__half2*)&v.y);
                    float4 fv = make_float4(f0.x, f0.y, f1.x, f1.y);
                    *(float4*)&patch[warp][lvl][r][cb * 4] = fv;
                }
            }
        }
    }
    __syncwarp();

    // Phase 2: bilinear combine
#pragma unroll
    for (int lvl = 0; lvl < 4; lvl++) {
        const int   w2  = wl[lvl];
        const float wm1 = wm1_[lvl];
        const float cxs = cxs_[lvl];
        const float cys = cys_[lvl];
        const int   xs4 = xs4_[lvl];
        const int   yst = yst_[lvl];
        float (*pp)[PROW] = patch[warp][lvl];

#pragma unroll
        for (int s = 0; s < 3; s++) {
            int t = lane + s * 32;
            if (t < 81) {
                const int ix = t / 9;
                const int iy = t - ix * 9;
                float x = fminf(fmaxf(cxs + (float)(ix - 4), 0.f), wm1);
                float y = fminf(fmaxf(cys + (float)(iy - 4), 0.f), wm1);
                float x0f = floorf(x), y0f = floorf(y);
                float fx = x - x0f, fy = y - y0f;
                int x0 = (int)x0f;
                int y0 = (int)y0f;
                int x1 = min(x0 + 1, w2 - 1) - xs4;
                int y1 = min(y0 + 1, w2 - 1) - yst;
                x0 -= xs4;
                y0 -= yst;

                float v00 = pp[y0][x0], v01 = pp[y0][x1];
                float v10 = pp[y1][x0], v11 = pp[y1][x1];
                float v = v00 * (1.f - fy) * (1.f - fx)
                        + v01 * (1.f - fy) * fx
                        + v10 * fy * (1.f - fx)
                        + v11 * fy * fx;
                outBase[lvl * 81 + t] = v;
            }
        }
    }
}

// ---------------------------------------------------------------------------
// Launch
// ---------------------------------------------------------------------------
extern "C" void kernel_launch(void* const* d_in, const int* in_sizes, int n_in,
                              void* d_out, int out_size) {
    const float* f1     = (const float*)d_in[0];
    const float* f2     = (const float*)d_in[1];
    const float* coords = (const float*)d_in[2];
    float* out          = (float*)d_out;

    prep_kernel<<<512 + 2048, 256>>>(f2, f1);
    bprep_kernel<<<dim3(QPAD / 32, Cc / 32, Bb), dim3(32, 8)>>>();

    cudaFuncSetAttribute(gemm_kernel, cudaFuncAttributeMaxDynamicSharedMemorySize, GEMM_SMEM);
    gemm_kernel<<<dim3(QPAD / 128, PTOT / 128, Bb), GT, GEMM_SMEM>>>();

    sample_kernel<<<Bb * HH * WW, 256>>>(coords, out);
}

// round 12
// speedup vs baseline: 1.1165x; 1.0305x over previous
#include <cuda_runtime.h>
#include <cuda_fp16.h>
#include <cstdint>

// ---------------------------------------------------------------------------
// CorrBlock: pooled-fmap2 fp16 HMMA GEMM (1-pass: Ahi*Bhi) + warp sampler.
// Round 12: sampler separable-metadata rewrite — per-level x/y interpolation
// tuples (frac + packed byte offsets) computed once by 18 lanes, phase 2 is
// pure table-lookup + 6-op bilinear. GEMM/preps unchanged (GEMM 73.3us opt).
// ---------------------------------------------------------------------------

#define Bb 2
#define Cc 256
#define HH 64
#define WW 64
#define NN 8
#define QTOT 5440
#define QPAD 5632      // 44 N-tiles of 128
#define PTOT 4096      // H*W

// Scratch (no cudaMalloc allowed)
__device__ __half g_Bt[(size_t)Bb * Cc * QTOT];           // 5.6 MB  [b][c][q] fp16
__device__ __half g_Ah[(size_t)Bb * PTOT * 256];          // 4.2 MB  [m][hi]
__device__ __half g_Bh[(size_t)Bb * QPAD * 256];          // 5.7 MB  [q][hi]
__device__ __half g_corrh[(size_t)Bb * PTOT * QTOT];      // 89 MB   fp16 corr

#define SWZ(o) ((o) ^ (((o) >> 3) & 0x70))

__device__ __forceinline__ uint32_t smem_to_u32(const void* p) {
    uint32_t a;
    asm("{ .reg .u64 t; cvta.to.shared.u64 t, %1; cvt.u32.u64 %0, t; }" : "=r"(a) : "l"(p));
    return a;
}
__device__ __forceinline__ void cp_async16(uint32_t dst, const void* src) {
    asm volatile("cp.async.cg.shared.global [%0], [%1], 16;" :: "r"(dst), "l"(src));
}
__device__ __forceinline__ void ldsm_x4(uint32_t* r, uint32_t addr) {
    asm volatile("ldmatrix.sync.aligned.m8n8.x4.shared.b16 {%0,%1,%2,%3}, [%4];"
                 : "=r"(r[0]), "=r"(r[1]), "=r"(r[2]), "=r"(r[3]) : "r"(addr));
}
__device__ __forceinline__ void mma16816(float* d, const uint32_t* a, uint32_t b0, uint32_t b1) {
    asm volatile("mma.sync.aligned.m16n8k16.row.col.f32.f16.f16.f32 "
                 "{%0,%1,%2,%3}, {%4,%5,%6,%7}, {%8,%9}, {%0,%1,%2,%3};"
                 : "+f"(d[0]), "+f"(d[1]), "+f"(d[2]), "+f"(d[3])
                 : "r"(a[0]), "r"(a[1]), "r"(a[2]), "r"(a[3]), "r"(b0), "r"(b1));
}

// ---------------------------------------------------------------------------
// Kernel 1: fused prep. Blocks [0,512): pool fmap2 -> fp16 g_Bt.
//           Blocks [512,2560): transpose f1 -> fp16 g_Ah. 256 threads.
// ---------------------------------------------------------------------------
__global__ __launch_bounds__(256) void prep_kernel(const float* __restrict__ f2,
                                                   const float* __restrict__ f1) {
    __shared__ float s0[4096];
    __shared__ float s1[1024];
    __shared__ float s2[256];
    __shared__ float tile[32][33];
    const int blk = blockIdx.x;
    const int tid = threadIdx.x;

    if (blk < 512) {
        int c = blk & 255, b = blk >> 8;
        const float* in = f2 + ((size_t)b * Cc + c) * (HH * WW);
        __half* outp = g_Bt + ((size_t)b * Cc + c) * QTOT;
        for (int i = tid; i < 1024; i += 256) {
            float4 v = ((const float4*)in)[i];
            ((float4*)s0)[i] = v;
            ((__half2*)outp)[2 * i]     = __floats2half2_rn(v.x, v.y);
            ((__half2*)outp)[2 * i + 1] = __floats2half2_rn(v.z, v.w);
        }
        __syncthreads();
        for (int o = tid; o < 1024; o += 256) {
            int y = o >> 5, x = o & 31;
            float v = 0.25f * (s0[(2*y)*64 + 2*x] + s0[(2*y)*64 + 2*x + 1]
                             + s0[(2*y+1)*64 + 2*x] + s0[(2*y+1)*64 + 2*x + 1]);
            s1[o] = v; outp[4096 + o] = __float2half_rn(v);
        }
        __syncthreads();
        {
            int y = tid >> 4, x = tid & 15;
            float v = 0.25f * (s1[(2*y)*32 + 2*x] + s1[(2*y)*32 + 2*x + 1]
                             + s1[(2*y+1)*32 + 2*x] + s1[(2*y+1)*32 + 2*x + 1]);
            s2[tid] = v; outp[5120 + tid] = __float2half_rn(v);
        }
        __syncthreads();
        if (tid < 64) {
            int y = tid >> 3, x = tid & 7;
            float v = 0.25f * (s2[(2*y)*16 + 2*x] + s2[(2*y)*16 + 2*x + 1]
                             + s2[(2*y+1)*16 + 2*x] + s2[(2*y+1)*16 + 2*x + 1]);
            outp[5376 + tid] = __float2half_rn(v);
        }
    } else {
        int blk2 = blk - 512;
        int p0 = (blk2 & 127) * 32;
        int c0 = ((blk2 >> 7) & 7) * 32;
        int b  = blk2 >> 10;
        int tx = tid & 31, ty = tid >> 5;
#pragma unroll
        for (int k = 0; k < 4; k++) {
            int c = c0 + ty + 8 * k;
            tile[ty + 8 * k][tx] = f1[((size_t)b * Cc + c) * PTOT + p0 + tx];
        }
        __syncthreads();
#pragma unroll
        for (int k = 0; k < 4; k++) {
            int p = p0 + ty + 8 * k, c = c0 + tx;
            g_Ah[((size_t)b * PTOT + p) * 256 + c] = __float2half_rn(tile[tx][ty + 8 * k]);
        }
    }
}

// ---------------------------------------------------------------------------
// Kernel 2: transpose g_Bt [b][c][q] fp16 -> [b][q][256], pad q>=5440
// ---------------------------------------------------------------------------
__global__ __launch_bounds__(256) void bprep_kernel() {
    __shared__ __half tile[32][34];
    int b = blockIdx.z, q0 = blockIdx.x * 32, c0 = blockIdx.y * 32;
    int tx = threadIdx.x, ty = threadIdx.y;
#pragma unroll
    for (int k = 0; k < 4; k++) {
        int c = c0 + ty + 8 * k, q = q0 + tx;
        tile[ty + 8 * k][tx] = (q < QTOT) ? g_Bt[((size_t)b * Cc + c) * QTOT + q]
                                          : __half(0.f);
    }
    __syncthreads();
#pragma unroll
    for (int k = 0; k < 4; k++) {
        int q = q0 + ty + 8 * k, c = c0 + tx;
        g_Bh[((size_t)b * QPAD + q) * 256 + c] = tile[tx][ty + 8 * k];
    }
}

// ---------------------------------------------------------------------------
// Kernel 3: HMMA GEMM (round-8 config, unchanged). CTA 128x128, BK=64, 4 chunks,
// 256 threads / 8 warps (warp tile 32x64), 3-stage cp.async, 2 CTAs/SM.
// grid (44, 32, 2).
// ---------------------------------------------------------------------------
#define GT 256
static constexpr int A_BYTES = 128 * 128;        // 16 KB
static constexpr int B_BYTES = 128 * 128;        // 16 KB
static constexpr int BUF_B = A_BYTES + B_BYTES;  // 32 KB
static constexpr int GEMM_SMEM = 3 * BUF_B;      // 96 KB

__global__ __launch_bounds__(GT, 2) void gemm_kernel() {
    extern __shared__ char smem[];
    const uint32_t sb = smem_to_u32(smem);
    const int tid = threadIdx.x, wid = tid >> 5, lid = tid & 31;
    const int b = blockIdx.z, m0 = blockIdx.y * 128, n0 = blockIdx.x * 128;
    const int warp_m = wid & 3, warp_n = wid >> 2;   // 4m x 2n warps, 32x64 each

    const __half* Ap = g_Ah + (size_t)b * PTOT * 256;
    const __half* Bp = g_Bh + (size_t)b * QPAD * 256;

    float acc[2][8][4];
#pragma unroll
    for (int i = 0; i < 2; i++)
#pragma unroll
        for (int j = 0; j < 8; j++)
#pragma unroll
            for (int k = 0; k < 4; k++) acc[i][j][k] = 0.f;

    auto issue_loads = [&](int c, int buf) {
        int k_off = c * 64;
        uint32_t aB = sb + buf * BUF_B;
        uint32_t bB = aB + A_BYTES;
#pragma unroll
        for (int i = 0; i < 8; i++) {
            int idx = tid + i * GT;               // 0..2047
            bool isB = idx >= 1024;
            int j = isB ? idx - 1024 : idx;
            int row = j >> 3, c16 = j & 7;
            const __half* src = isB
                ? Bp + (size_t)(n0 + row) * 256 + k_off + c16 * 8
                : Ap + (size_t)(m0 + row) * 256 + k_off + c16 * 8;
            uint32_t dst = (isB ? bB : aB) + SWZ((uint32_t)(row * 128 + c16 * 16));
            cp_async16(dst, src);
        }
        asm volatile("cp.async.commit_group;" ::: "memory");
    };

    issue_loads(0, 0);
    issue_loads(1, 1);

    const int a_row = warp_m * 32 + (lid & 15);
    const int a_kb  = (lid >> 4) * 16;
    const int b_row = warp_n * 64 + ((lid >> 4) & 1) * 8 + (lid & 7);
    const int b_kb  = ((lid >> 3) & 1) * 16;

    for (int c = 0; c < 4; c++) {
        if (c < 3) asm volatile("cp.async.wait_group 1;" ::: "memory");
        else       asm volatile("cp.async.wait_group 0;" ::: "memory");
        __syncthreads();
        if (c < 2) issue_loads(c + 2, (c + 2) % 3);

        uint32_t aB = sb + (c % 3) * BUF_B;
        uint32_t bB = aB + A_BYTES;

#pragma unroll
        for (int ks = 0; ks < 4; ks++) {
            uint32_t af[2][4];
            uint32_t aAddr = aB + SWZ((uint32_t)(a_row * 128 + ks * 32 + a_kb));
            ldsm_x4(af[0], aAddr);
            ldsm_x4(af[1], aAddr + 2048);        // +16 rows

            uint32_t bf[4][4];
            uint32_t bAddr = bB + SWZ((uint32_t)(b_row * 128 + ks * 32 + b_kb));
#pragma unroll
            for (int p = 0; p < 4; p++) ldsm_x4(bf[p], bAddr + p * 2048);

#pragma unroll
            for (int mb = 0; mb < 2; mb++)
#pragma unroll
                for (int nb = 0; nb < 8; nb++)
                    mma16816(acc[mb][nb], af[mb],
                             bf[nb >> 1][(nb & 1) * 2], bf[nb >> 1][(nb & 1) * 2 + 1]);
        }
    }

    const float scale = 0.0625f;
    const int rbase = m0 + warp_m * 32 + (lid >> 2);
    const int cbase = n0 + warp_n * 64 + (lid & 3) * 2;
#pragma unroll
    for (int mb = 0; mb < 2; mb++) {
#pragma unroll
        for (int nb = 0; nb < 8; nb++) {
            int q = cbase + nb * 8;
            if (q < QTOT) {
                int r0 = rbase + mb * 16;
                __half* c0p = g_corrh + ((size_t)b * PTOT + r0) * QTOT + q;
                __half* c1p = c0p + (size_t)8 * QTOT;
                *(__half2*)c0p = __floats2half2_rn(acc[mb][nb][0] * scale,
                                                   acc[mb][nb][1] * scale);
                *(__half2*)c1p = __floats2half2_rn(acc[mb][nb][2] * scale,
                                                   acc[mb][nb][3] * scale);
            }
        }
    }
}

// ---------------------------------------------------------------------------
// Kernel 4: sampler. One 256-thr block = 8 warps = 8 n-heads of one (b,h,w).
// Phase 1 loads patches AND precomputes per-level separable interpolation
// metadata (9 x-tuples by lanes 0-8, 9 y-tuples by lanes 16-24):
//   {frac, packed byte offsets (lo|hi<<16), prescaled: x *4B, y *80B}.
// Phase 2 per output: 2x LDS.64 metadata + 4 patch LDS + 6-op bilinear.
// grid 8192.
// ---------------------------------------------------------------------------
#define PROW 20
__global__ __launch_bounds__(256) void sample_kernel(const float* __restrict__ coords,
                                                     float* __restrict__ out) {
    const int warp = threadIdx.x >> 5;          // = n (0..7)
    const int lane = threadIdx.x & 31;
    const int bhw = blockIdx.x;                  // b*4096 + h*64 + w
    const int b = bhw >> 12;
    const int hw = bhw & 4095;
    const int h = hw >> 6;
    const int w = hw & 63;
    const int n = warp;
    const int qid = ((b * NN + n) << 12) | hw;

    __shared__ float  patch[8][4][10][PROW];    // [warp][lvl][row][col(padded)]
    __shared__ float2 xdat[8][4][9];            // {fx, x0*4 | x1*4 <<16}
    __shared__ float2 ydat[8][4][9];            // {fy, y0*80 | y1*80 <<16}

    const float cx = coords[((((size_t)b * NN + n) * 2 + 0) * HH + h) * WW + w];
    const float cy = coords[((((size_t)b * NN + n) * 2 + 1) * HH + h) * WW + w];

    const __half* corrRow = g_corrh + ((size_t)b * PTOT + hw) * QTOT;
    float* outBase = out + (size_t)qid * 324;

    const int   lvl_off[4] = {0, 4096, 5120, 5376};
    const int   wl[4]      = {64, 32, 16, 8};
    const float inv[4]     = {1.f, 0.5f, 0.25f, 0.125f};

    // Phase 1: patch loads + metadata precompute, per level (static lvl)
#pragma unroll
    for (int lvl = 0; lvl < 4; lvl++) {
        const int   w2  = wl[lvl];
        const float wm1 = (float)(w2 - 1);
        const float cxs = cx * inv[lvl];
        const float cys = cy * inv[lvl];
        const float ylo = fminf(fmaxf(cys - 4.f, 0.f), wm1);
        const float yhi = fminf(fmaxf(cys + 4.f, 0.f), wm1);
        const float xlo = fminf(fmaxf(cxs - 4.f, 0.f), wm1);
        const int xstart = (int)floorf(xlo);
        const int ystart = (int)floorf(ylo);
        const int yend   = min((int)floorf(yhi) + 1, w2 - 1);
        const int xs4    = xstart & ~3;

        const __half* lbase = corrRow + lvl_off[lvl];
        // patch loads: 40 float4 slots over lanes (lane, lane+32)
#pragma unroll
        for (int s = 0; s < 2; s++) {
            int slot = lane + s * 32;
            if (slot < 40) {
                int r = slot >> 2, cb = slot & 3;
                int col = xs4 + cb * 4;
                if (r <= yend - ystart && col < w2) {
                    uint2 v = *(const uint2*)(lbase + (ystart + r) * w2 + col);
                    float2 f0 = __half22float2(*(__half2*)&v.x);
                    float2 f1 = __half22float2(*(__half2*)&v.y);
                    float4 fv = make_float4(f0.x, f0.y, f1.x, f1.y);
                    *(float4*)&patch[warp][lvl][r][cb * 4] = fv;
                }
            }
        }
        // metadata: lanes 0-8 -> x, lanes 16-24 -> y
        {
            int grp = lane >> 4;                 // 0: x, 1: y
            int off = lane & 15;
            if (off < 9 && grp < 2) {
                float c   = grp ? cys : cxs;
                int   sub = grp ? ystart : xs4;
                int   str = grp ? (PROW * 4) : 4;
                float v   = fminf(fmaxf(c + (float)(off - 4), 0.f), wm1);
                float v0f = floorf(v);
                float f   = v - v0f;
                int   i0  = (int)v0f;
                int   i1  = min(i0 + 1, w2 - 1);
                uint32_t packed = (uint32_t)((i0 - sub) * str)
                                | ((uint32_t)((i1 - sub) * str) << 16);
                float2 md = make_float2(f, __uint_as_float(packed));
                if (grp) ydat[warp][lvl][off] = md;
                else     xdat[warp][lvl][off] = md;
            }
        }
    }
    __syncwarp();

    // Phase 2: table-driven separable bilinear
#pragma unroll
    for (int s = 0; s < 3; s++) {
        int t = lane + s * 32;
        if (t < 81) {
            int ix = t / 9;
            int iy = t - ix * 9;
#pragma unroll
            for (int lvl = 0; lvl < 4; lvl++) {
                float2 xd = xdat[warp][lvl][ix];
                float2 yd = ydat[warp][lvl][iy];
                uint32_t xp = __float_as_uint(xd.y);
                uint32_t yp = __float_as_uint(yd.y);
                const char* pb = (const char*)&patch[warp][lvl][0][0];
                uint32_t y0o = yp & 0xFFFFu, y1o = yp >> 16;
                uint32_t x0o = xp & 0xFFFFu, x1o = xp >> 16;
                float v00 = *(const float*)(pb + y0o + x0o);
                float v01 = *(const float*)(pb + y0o + x1o);
                float v10 = *(const float*)(pb + y1o + x0o);
                float v11 = *(const float*)(pb + y1o + x1o);
                float h0 = fmaf(xd.x, v01 - v00, v00);
                float h1 = fmaf(xd.x, v11 - v10, v10);
                outBase[lvl * 81 + t] = fmaf(yd.x, h1 - h0, h0);
            }
        }
    }
}

// ---------------------------------------------------------------------------
// Launch
// ---------------------------------------------------------------------------
extern "C" void kernel_launch(void* const* d_in, const int* in_sizes, int n_in,
                              void* d_out, int out_size) {
    const float* f1     = (const float*)d_in[0];
    const float* f2     = (const float*)d_in[1];
    const float* coords = (const float*)d_in[2];
    float* out          = (float*)d_out;

    prep_kernel<<<512 + 2048, 256>>>(f2, f1);
    bprep_kernel<<<dim3(QPAD / 32, Cc / 32, Bb), dim3(32, 8)>>>();

    cudaFuncSetAttribute(gemm_kernel, cudaFuncAttributeMaxDynamicSharedMemorySize, GEMM_SMEM);
    gemm_kernel<<<dim3(QPAD / 128, PTOT / 128, Bb), GT, GEMM_SMEM>>>();

    sample_kernel<<<Bb * HH * WW, 256>>>(coords, out);
}

// round 13
// speedup vs baseline: 1.1328x; 1.0146x over previous
#include <cuda_runtime.h>
#include <cuda_fp16.h>
#include <cstdint>

// ---------------------------------------------------------------------------
// CorrBlock: pooled-fmap2 fp16 HMMA GEMM (1-pass: Ahi*Bhi) + warp sampler.
// Round 13: both GEMM operands consumed K-major via ldmatrix.trans ->
//   bprep kernel deleted; aprep is a plain fp32->fp16 copy (no transpose).
//   Sampler ydat packs absolute smem offsets (fewer IADDs in hot loop).
// GEMM core (tile shape, pipeline, mma, epilogue) unchanged from round 8.
// ---------------------------------------------------------------------------

#define Bb 2
#define Cc 256
#define HH 64
#define WW 64
#define NN 8
#define QTOT 5440
#define QPAD 5632      // 44 N-tiles of 128 (stride; pad region = don't-care)
#define PTOT 4096      // H*W

// Scratch (no cudaMalloc allowed)
__device__ __half g_Bt[(size_t)Bb * Cc * QPAD];           // 5.8 MB [b][c][QPAD] fp16
__device__ __half g_Ah[(size_t)Bb * Cc * PTOT];           // 4.2 MB [b][c][m] fp16
__device__ __half g_corrh[(size_t)Bb * PTOT * QTOT];      // 89 MB  fp16 corr

// swizzle for 256B rows: 16B-unit index ^= (krow & 7)
#define SWZ256(o) ((o) ^ ((((o) >> 8) & 7) << 4))

__device__ __forceinline__ uint32_t smem_to_u32(const void* p) {
    uint32_t a;
    asm("{ .reg .u64 t; cvta.to.shared.u64 t, %1; cvt.u32.u64 %0, t; }" : "=r"(a) : "l"(p));
    return a;
}
__device__ __forceinline__ void cp_async16(uint32_t dst, const void* src) {
    asm volatile("cp.async.cg.shared.global [%0], [%1], 16;" :: "r"(dst), "l"(src));
}
__device__ __forceinline__ void ldsm_x4_trans(uint32_t* r, uint32_t addr) {
    asm volatile("ldmatrix.sync.aligned.m8n8.x4.trans.shared.b16 {%0,%1,%2,%3}, [%4];"
                 : "=r"(r[0]), "=r"(r[1]), "=r"(r[2]), "=r"(r[3]) : "r"(addr));
}
__device__ __forceinline__ void mma16816(float* d, const uint32_t* a, uint32_t b0, uint32_t b1) {
    asm volatile("mma.sync.aligned.m16n8k16.row.col.f32.f16.f16.f32 "
                 "{%0,%1,%2,%3}, {%4,%5,%6,%7}, {%8,%9}, {%0,%1,%2,%3};"
                 : "+f"(d[0]), "+f"(d[1]), "+f"(d[2]), "+f"(d[3])
                 : "r"(a[0]), "r"(a[1]), "r"(a[2]), "r"(a[3]), "r"(b0), "r"(b1));
}

// ---------------------------------------------------------------------------
// Kernel 1: fused prep. Blocks [0,512): pool fmap2 -> fp16 g_Bt (stride QPAD).
//           Blocks [512,1536): fp32->fp16 copy of f1 into g_Ah. 256 threads.
// ---------------------------------------------------------------------------
__global__ __launch_bounds__(256) void prep_kernel(const float* __restrict__ f2,
                                                   const float* __restrict__ f1) {
    __shared__ float s0[4096];
    __shared__ float s1[1024];
    __shared__ float s2[256];
    const int blk = blockIdx.x;
    const int tid = threadIdx.x;

    if (blk < 512) {
        int c = blk & 255, b = blk >> 8;
        const float* in = f2 + ((size_t)b * Cc + c) * (HH * WW);
        __half* outp = g_Bt + ((size_t)b * Cc + c) * QPAD;
        for (int i = tid; i < 1024; i += 256) {
            float4 v = ((const float4*)in)[i];
            ((float4*)s0)[i] = v;
            ((__half2*)outp)[2 * i]     = __floats2half2_rn(v.x, v.y);
            ((__half2*)outp)[2 * i + 1] = __floats2half2_rn(v.z, v.w);
        }
        __syncthreads();
        for (int o = tid; o < 1024; o += 256) {
            int y = o >> 5, x = o & 31;
            float v = 0.25f * (s0[(2*y)*64 + 2*x] + s0[(2*y)*64 + 2*x + 1]
                             + s0[(2*y+1)*64 + 2*x] + s0[(2*y+1)*64 + 2*x + 1]);
            s1[o] = v; outp[4096 + o] = __float2half_rn(v);
        }
        __syncthreads();
        {
            int y = tid >> 4, x = tid & 15;
            float v = 0.25f * (s1[(2*y)*32 + 2*x] + s1[(2*y)*32 + 2*x + 1]
                             + s1[(2*y+1)*32 + 2*x] + s1[(2*y+1)*32 + 2*x + 1]);
            s2[tid] = v; outp[5120 + tid] = __float2half_rn(v);
        }
        __syncthreads();
        if (tid < 64) {
            int y = tid >> 3, x = tid & 7;
            float v = 0.25f * (s2[(2*y)*16 + 2*x] + s2[(2*y)*16 + 2*x + 1]
                             + s2[(2*y+1)*16 + 2*x] + s2[(2*y+1)*16 + 2*x + 1]);
            outp[5376 + tid] = __float2half_rn(v);
        }
    } else {
        // plain fp32->fp16 convert of f1 (layout preserved [b][c][m])
        int blk2 = blk - 512;                    // 0..1023
        size_t base = (size_t)blk2 * 512 + tid * 2;   // float4 units (total 524288)
#pragma unroll
        for (int i = 0; i < 2; i++) {
            float4 v = ((const float4*)f1)[base + i];
            ((__half2*)g_Ah)[(base + i) * 2]     = __floats2half2_rn(v.x, v.y);
            ((__half2*)g_Ah)[(base + i) * 2 + 1] = __floats2half2_rn(v.z, v.w);
        }
    }
}

// ---------------------------------------------------------------------------
// Kernel 2: HMMA GEMM. CTA 128x128, BK=64, K'=256 (4 chunks), 256 thr / 8 warps
// (warp tile 32x64), 3-stage cp.async, 2 CTAs/SM. Operands K-major in smem
// ([k=64 rows][256B]), consumed via ldmatrix.trans. grid (44, 32, 2).
// ---------------------------------------------------------------------------
#define GT 256
static constexpr int A_BYTES = 64 * 256;         // 16 KB  [k][m]
static constexpr int B_BYTES = 64 * 256;         // 16 KB  [k][n]
static constexpr int BUF_B = A_BYTES + B_BYTES;  // 32 KB
static constexpr int GEMM_SMEM = 3 * BUF_B;      // 96 KB

__global__ __launch_bounds__(GT, 2) void gemm_kernel() {
    extern __shared__ char smem[];
    const uint32_t sb = smem_to_u32(smem);
    const int tid = threadIdx.x, wid = tid >> 5, lid = tid & 31;
    const int b = blockIdx.z, m0 = blockIdx.y * 128, n0 = blockIdx.x * 128;
    const int warp_m = wid & 3, warp_n = wid >> 2;   // 4m x 2n warps, 32x64 each

    const __half* Ap = g_Ah + (size_t)b * Cc * PTOT;   // [c][m]
    const __half* Bp = g_Bt + (size_t)b * Cc * QPAD;   // [c][q]

    float acc[2][8][4];
#pragma unroll
    for (int i = 0; i < 2; i++)
#pragma unroll
        for (int j = 0; j < 8; j++)
#pragma unroll
            for (int k = 0; k < 4; k++) acc[i][j][k] = 0.f;

    // async load of chunk c (k rows c*64..c*64+63) into buffer `buf`
    auto issue_loads = [&](int c, int buf) {
        int k_off = c * 64;
        uint32_t aB = sb + buf * BUF_B;
        uint32_t bB = aB + A_BYTES;
#pragma unroll
        for (int i = 0; i < 8; i++) {
            int idx = tid + i * GT;               // 0..2047
            bool isB = idx >= 1024;
            int j = isB ? idx - 1024 : idx;
            int row = j >> 4, u = j & 15;         // k-row, 16B unit
            const __half* src = isB
                ? Bp + (size_t)(k_off + row) * QPAD + n0 + u * 8
                : Ap + (size_t)(k_off + row) * PTOT + m0 + u * 8;
            uint32_t dst = (isB ? bB : aB) + row * 256 + ((u ^ (row & 7)) << 4);
            cp_async16(dst, src);
        }
        asm volatile("cp.async.commit_group;" ::: "memory");
    };

    issue_loads(0, 0);
    issue_loads(1, 1);

    // trans-ldsm lane components (mapping mirrors the verified non-trans tiles)
    const int krowA = ((lid >> 4) & 1) * 8 + (lid & 7);   // A: g2/g3 -> k+8
    const int mbyteA = ((lid >> 3) & 1) * 16;             // A: g1/g3 -> m+8
    const int krowB = ((lid >> 3) & 1) * 8 + (lid & 7);   // B: g1/g3 -> k+8
    const int nbyteB = ((lid >> 4) & 1) * 16;             // B: g2/g3 -> n+8

    for (int c = 0; c < 4; c++) {
        if (c < 3) asm volatile("cp.async.wait_group 1;" ::: "memory");
        else       asm volatile("cp.async.wait_group 0;" ::: "memory");
        __syncthreads();
        if (c < 2) issue_loads(c + 2, (c + 2) % 3);

        uint32_t aB = sb + (c % 3) * BUF_B;
        uint32_t bB = aB + A_BYTES;

#pragma unroll
        for (int ks = 0; ks < 4; ks++) {
            uint32_t af[2][4];
#pragma unroll
            for (int mb = 0; mb < 2; mb++) {
                uint32_t off = (uint32_t)((ks * 16 + krowA) * 256
                                          + warp_m * 64 + mb * 32 + mbyteA);
                ldsm_x4_trans(af[mb], aB + SWZ256(off));
            }
            uint32_t bf[4][4];
#pragma unroll
            for (int p = 0; p < 4; p++) {
                uint32_t off = (uint32_t)((ks * 16 + krowB) * 256
                                          + warp_n * 128 + p * 32 + nbyteB);
                ldsm_x4_trans(bf[p], bB + SWZ256(off));
            }
#pragma unroll
            for (int mb = 0; mb < 2; mb++)
#pragma unroll
                for (int nb = 0; nb < 8; nb++)
                    mma16816(acc[mb][nb], af[mb],
                             bf[nb >> 1][(nb & 1) * 2], bf[nb >> 1][(nb & 1) * 2 + 1]);
        }
    }

    const float scale = 0.0625f;
    const int rbase = m0 + warp_m * 32 + (lid >> 2);
    const int cbase = n0 + warp_n * 64 + (lid & 3) * 2;
#pragma unroll
    for (int mb = 0; mb < 2; mb++) {
#pragma unroll
        for (int nb = 0; nb < 8; nb++) {
            int q = cbase + nb * 8;
            if (q < QTOT) {
                int r0 = rbase + mb * 16;
                __half* c0p = g_corrh + ((size_t)b * PTOT + r0) * QTOT + q;
                __half* c1p = c0p + (size_t)8 * QTOT;
                *(__half2*)c0p = __floats2half2_rn(acc[mb][nb][0] * scale,
                                                   acc[mb][nb][1] * scale);
                *(__half2*)c1p = __floats2half2_rn(acc[mb][nb][2] * scale,
                                                   acc[mb][nb][3] * scale);
            }
        }
    }
}

// ---------------------------------------------------------------------------
// Kernel 3: sampler. 256-thr block = 8 warps = 8 n-heads of one (b,h,w).
// ydat packs ABSOLUTE patch byte offsets (base folded in); xdat relative.
// grid 8192.
// ---------------------------------------------------------------------------
#define PROW 20
__global__ __launch_bounds__(256) void sample_kernel(const float* __restrict__ coords,
                                                     float* __restrict__ out) {
    const int warp = threadIdx.x >> 5;          // = n (0..7)
    const int lane = threadIdx.x & 31;
    const int bhw = blockIdx.x;                  // b*4096 + h*64 + w
    const int b = bhw >> 12;
    const int hw = bhw & 4095;
    const int h = hw >> 6;
    const int w = hw & 63;
    const int n = warp;
    const int qid = ((b * NN + n) << 12) | hw;

    __shared__ float  patch[8][4][10][PROW];    // [warp][lvl][row][col(padded)]
    __shared__ float2 xdat[8][4][9];            // {fx, x0*4 | x1*4 <<16}
    __shared__ float2 ydat[8][4][9];            // {fy, abs(y0) | abs(y1) <<16}

    const float cx = coords[((((size_t)b * NN + n) * 2 + 0) * HH + h) * WW + w];
    const float cy = coords[((((size_t)b * NN + n) * 2 + 1) * HH + h) * WW + w];

    const __half* corrRow = g_corrh + ((size_t)b * PTOT + hw) * QTOT;
    float* outBase = out + (size_t)qid * 324;

    const int   lvl_off[4] = {0, 4096, 5120, 5376};
    const int   wl[4]      = {64, 32, 16, 8};
    const float inv[4]     = {1.f, 0.5f, 0.25f, 0.125f};

    // Phase 1: patch loads + separable metadata
#pragma unroll
    for (int lvl = 0; lvl < 4; lvl++) {
        const int   w2  = wl[lvl];
        const float wm1 = (float)(w2 - 1);
        const float cxs = cx * inv[lvl];
        const float cys = cy * inv[lvl];
        const float ylo = fminf(fmaxf(cys - 4.f, 0.f), wm1);
        const float yhi = fminf(fmaxf(cys + 4.f, 0.f), wm1);
        const float xlo = fminf(fmaxf(cxs - 4.f, 0.f), wm1);
        const int xstart = (int)floorf(xlo);
        const int ystart = (int)floorf(ylo);
        const int yend   = min((int)floorf(yhi) + 1, w2 - 1);
        const int xs4    = xstart & ~3;

        const __half* lbase = corrRow + lvl_off[lvl];
#pragma unroll
        for (int s = 0; s < 2; s++) {
            int slot = lane + s * 32;
            if (slot < 40) {
                int r = slot >> 2, cb = slot & 3;
                int col = xs4 + cb * 4;
                if (r <= yend - ystart && col < w2) {
                    uint2 v = *(const uint2*)(lbase + (ystart + r) * w2 + col);
                    float2 f0 = __half22float2(*(__half2*)&v.x);
                    float2 f1 = __half22float2(*(__half2*)&v.y);
                    float4 fv = make_float4(f0.x, f0.y, f1.x, f1.y);
                    *(float4*)&patch[warp][lvl][r][cb * 4] = fv;
                }
            }
        }
        // metadata: lanes 0-8 -> x (relative), lanes 16-24 -> y (absolute)
        {
            int grp = lane >> 4;
            int off = lane & 15;
            if (off < 9 && grp < 2) {
                float c   = grp ? cys : cxs;
                int   sub = grp ? ystart : xs4;
                int   str = grp ? (PROW * 4) : 4;
                int   bas = grp ? (warp * 4 + lvl) * (10 * PROW * 4) : 0;
                float v   = fminf(fmaxf(c + (float)(off - 4), 0.f), wm1);
                float v0f = floorf(v);
                float f   = v - v0f;
                int   i0  = (int)v0f;
                int   i1  = min(i0 + 1, w2 - 1);
                uint32_t packed = (uint32_t)(bas + (i0 - sub) * str)
                                | ((uint32_t)(bas + (i1 - sub) * str) << 16);
                float2 md = make_float2(f, __uint_as_float(packed));
                if (grp) ydat[warp][lvl][off] = md;
                else     xdat[warp][lvl][off] = md;
            }
        }
    }
    __syncwarp();

    // Phase 2: table-driven separable bilinear
    const char* pb = (const char*)&patch[0][0][0][0];
#pragma unroll
    for (int s = 0; s < 3; s++) {
        int t = lane + s * 32;
        if (t < 81) {
            int ix = t / 9;
            int iy = t - ix * 9;
#pragma unroll
            for (int lvl = 0; lvl < 4; lvl++) {
                float2 xd = xdat[warp][lvl][ix];
                float2 yd = ydat[warp][lvl][iy];
                uint32_t xp = __float_as_uint(xd.y);
                uint32_t yp = __float_as_uint(yd.y);
                uint32_t y0o = yp & 0xFFFFu, y1o = yp >> 16;
                uint32_t x0o = xp & 0xFFFFu, x1o = xp >> 16;
                float v00 = *(const float*)(pb + y0o + x0o);
                float v01 = *(const float*)(pb + y0o + x1o);
                float v10 = *(const float*)(pb + y1o + x0o);
                float v11 = *(const float*)(pb + y1o + x1o);
                float h0 = fmaf(xd.x, v01 - v00, v00);
                float h1 = fmaf(xd.x, v11 - v10, v10);
                outBase[lvl * 81 + t] = fmaf(yd.x, h1 - h0, h0);
            }
        }
    }
}

// ---------------------------------------------------------------------------
// Launch
// ---------------------------------------------------------------------------
extern "C" void kernel_launch(void* const* d_in, const int* in_sizes, int n_in,
                              void* d_out, int out_size) {
    const float* f1     = (const float*)d_in[0];
    const float* f2     = (const float*)d_in[1];
    const float* coords = (const float*)d_in[2];
    float* out          = (float*)d_out;

    prep_kernel<<<512 + 1024, 256>>>(f2, f1);

    cudaFuncSetAttribute(gemm_kernel, cudaFuncAttributeMaxDynamicSharedMemorySize, GEMM_SMEM);
    gemm_kernel<<<dim3(QPAD / 128, PTOT / 128, Bb), GT, GEMM_SMEM>>>();

    sample_kernel<<<Bb * HH * WW, 256>>>(coords, out);
}

// round 14
// speedup vs baseline: 1.1363x; 1.0031x over previous
#include <cuda_runtime.h>
#include <cuda_fp16.h>
#include <cstdint>

// ---------------------------------------------------------------------------
// CorrBlock: pooled-fmap2 fp16 HMMA GEMM (1-pass: Ahi*Bhi) + warp sampler.
// Round 14: sampler patch stored as overlapping half2 PAIRS (v[x],v[x+1]) ->
//   both x-corners in one LDS.32; phase-2 LDS count cut 33%. Pairs built at
//   load time with 2 PRMT + 1 shfl (cross-chunk element from neighbor lane).
// GEMM + prep unchanged (round-13, measured optima).
// ---------------------------------------------------------------------------

#define Bb 2
#define Cc 256
#define HH 64
#define WW 64
#define NN 8
#define QTOT 5440
#define QPAD 5632      // stride; pad region = don't-care
#define PTOT 4096      // H*W

// Scratch (no cudaMalloc allowed)
__device__ __half g_Bt[(size_t)Bb * Cc * QPAD];           // 5.8 MB [b][c][QPAD] fp16
__device__ __half g_Ah[(size_t)Bb * Cc * PTOT];           // 4.2 MB [b][c][m] fp16
__device__ __half g_corrh[(size_t)Bb * PTOT * QTOT];      // 89 MB  fp16 corr

__device__ __forceinline__ uint32_t smem_to_u32(const void* p) {
    uint32_t a;
    asm("{ .reg .u64 t; cvta.to.shared.u64 t, %1; cvt.u32.u64 %0, t; }" : "=r"(a) : "l"(p));
    return a;
}
__device__ __forceinline__ void cp_async16(uint32_t dst, const void* src) {
    asm volatile("cp.async.cg.shared.global [%0], [%1], 16;" :: "r"(dst), "l"(src));
}
__device__ __forceinline__ void ldsm_x4_trans(uint32_t* r, uint32_t addr) {
    asm volatile("ldmatrix.sync.aligned.m8n8.x4.trans.shared.b16 {%0,%1,%2,%3}, [%4];"
                 : "=r"(r[0]), "=r"(r[1]), "=r"(r[2]), "=r"(r[3]) : "r"(addr));
}
__device__ __forceinline__ void mma16816(float* d, const uint32_t* a, uint32_t b0, uint32_t b1) {
    asm volatile("mma.sync.aligned.m16n8k16.row.col.f32.f16.f16.f32 "
                 "{%0,%1,%2,%3}, {%4,%5,%6,%7}, {%8,%9}, {%0,%1,%2,%3};"
                 : "+f"(d[0]), "+f"(d[1]), "+f"(d[2]), "+f"(d[3])
                 : "r"(a[0]), "r"(a[1]), "r"(a[2]), "r"(a[3]), "r"(b0), "r"(b1));
}

// ---------------------------------------------------------------------------
// Kernel 1: fused prep (unchanged). Blocks [0,512): pool fmap2 -> fp16 g_Bt.
//           Blocks [512,1536): fp32->fp16 copy of f1 into g_Ah. 256 threads.
// ---------------------------------------------------------------------------
__global__ __launch_bounds__(256) void prep_kernel(const float* __restrict__ f2,
                                                   const float* __restrict__ f1) {
    __shared__ float s0[4096];
    __shared__ float s1[1024];
    __shared__ float s2[256];
    const int blk = blockIdx.x;
    const int tid = threadIdx.x;

    if (blk < 512) {
        int c = blk & 255, b = blk >> 8;
        const float* in = f2 + ((size_t)b * Cc + c) * (HH * WW);
        __half* outp = g_Bt + ((size_t)b * Cc + c) * QPAD;
        for (int i = tid; i < 1024; i += 256) {
            float4 v = ((const float4*)in)[i];
            ((float4*)s0)[i] = v;
            ((__half2*)outp)[2 * i]     = __floats2half2_rn(v.x, v.y);
            ((__half2*)outp)[2 * i + 1] = __floats2half2_rn(v.z, v.w);
        }
        __syncthreads();
        for (int o = tid; o < 1024; o += 256) {
            int y = o >> 5, x = o & 31;
            float v = 0.25f * (s0[(2*y)*64 + 2*x] + s0[(2*y)*64 + 2*x + 1]
                             + s0[(2*y+1)*64 + 2*x] + s0[(2*y+1)*64 + 2*x + 1]);
            s1[o] = v; outp[4096 + o] = __float2half_rn(v);
        }
        __syncthreads();
        {
            int y = tid >> 4, x = tid & 15;
            float v = 0.25f * (s1[(2*y)*32 + 2*x] + s1[(2*y)*32 + 2*x + 1]
                             + s1[(2*y+1)*32 + 2*x] + s1[(2*y+1)*32 + 2*x + 1]);
            s2[tid] = v; outp[5120 + tid] = __float2half_rn(v);
        }
        __syncthreads();
        if (tid < 64) {
            int y = tid >> 3, x = tid & 7;
            float v = 0.25f * (s2[(2*y)*16 + 2*x] + s2[(2*y)*16 + 2*x + 1]
                             + s2[(2*y+1)*16 + 2*x] + s2[(2*y+1)*16 + 2*x + 1]);
            outp[5376 + tid] = __float2half_rn(v);
        }
    } else {
        int blk2 = blk - 512;                    // 0..1023
        size_t base = (size_t)blk2 * 512 + tid * 2;   // float4 units
#pragma unroll
        for (int i = 0; i < 2; i++) {
            float4 v = ((const float4*)f1)[base + i];
            ((__half2*)g_Ah)[(base + i) * 2]     = __floats2half2_rn(v.x, v.y);
            ((__half2*)g_Ah)[(base + i) * 2 + 1] = __floats2half2_rn(v.z, v.w);
        }
    }
}

// ---------------------------------------------------------------------------
// Kernel 2: HMMA GEMM (round-13, unchanged). CTA 128x128, BK=64, 4 chunks,
// 256 thr / 8 warps (32x64), 3-stage cp.async, 2 CTAs/SM, trans-ldsm operands.
// grid (44, 32, 2).
// ---------------------------------------------------------------------------
#define GT 256
static constexpr int A_BYTES = 64 * 256;         // 16 KB  [k][m]
static constexpr int B_BYTES = 64 * 256;         // 16 KB  [k][n]
static constexpr int BUF_B = A_BYTES + B_BYTES;  // 32 KB
static constexpr int GEMM_SMEM = 3 * BUF_B;      // 96 KB
#define SWZ256(o) ((o) ^ ((((o) >> 8) & 7) << 4))

__global__ __launch_bounds__(GT, 2) void gemm_kernel() {
    extern __shared__ char smem[];
    const uint32_t sb = smem_to_u32(smem);
    const int tid = threadIdx.x, wid = tid >> 5, lid = tid & 31;
    const int b = blockIdx.z, m0 = blockIdx.y * 128, n0 = blockIdx.x * 128;
    const int warp_m = wid & 3, warp_n = wid >> 2;

    const __half* Ap = g_Ah + (size_t)b * Cc * PTOT;
    const __half* Bp = g_Bt + (size_t)b * Cc * QPAD;

    float acc[2][8][4];
#pragma unroll
    for (int i = 0; i < 2; i++)
#pragma unroll
        for (int j = 0; j < 8; j++)
#pragma unroll
            for (int k = 0; k < 4; k++) acc[i][j][k] = 0.f;

    auto issue_loads = [&](int c, int buf) {
        int k_off = c * 64;
        uint32_t aB = sb + buf * BUF_B;
        uint32_t bB = aB + A_BYTES;
#pragma unroll
        for (int i = 0; i < 8; i++) {
            int idx = tid + i * GT;
            bool isB = idx >= 1024;
            int j = isB ? idx - 1024 : idx;
            int row = j >> 4, u = j & 15;
            const __half* src = isB
                ? Bp + (size_t)(k_off + row) * QPAD + n0 + u * 8
                : Ap + (size_t)(k_off + row) * PTOT + m0 + u * 8;
            uint32_t dst = (isB ? bB : aB) + row * 256 + ((u ^ (row & 7)) << 4);
            cp_async16(dst, src);
        }
        asm volatile("cp.async.commit_group;" ::: "memory");
    };

    issue_loads(0, 0);
    issue_loads(1, 1);

    const int krowA = ((lid >> 4) & 1) * 8 + (lid & 7);
    const int mbyteA = ((lid >> 3) & 1) * 16;
    const int krowB = ((lid >> 3) & 1) * 8 + (lid & 7);
    const int nbyteB = ((lid >> 4) & 1) * 16;

    for (int c = 0; c < 4; c++) {
        if (c < 3) asm volatile("cp.async.wait_group 1;" ::: "memory");
        else       asm volatile("cp.async.wait_group 0;" ::: "memory");
        __syncthreads();
        if (c < 2) issue_loads(c + 2, (c + 2) % 3);

        uint32_t aB = sb + (c % 3) * BUF_B;
        uint32_t bB = aB + A_BYTES;

#pragma unroll
        for (int ks = 0; ks < 4; ks++) {
            uint32_t af[2][4];
#pragma unroll
            for (int mb = 0; mb < 2; mb++) {
                uint32_t off = (uint32_t)((ks * 16 + krowA) * 256
                                          + warp_m * 64 + mb * 32 + mbyteA);
                ldsm_x4_trans(af[mb], aB + SWZ256(off));
            }
            uint32_t bf[4][4];
#pragma unroll
            for (int p = 0; p < 4; p++) {
                uint32_t off = (uint32_t)((ks * 16 + krowB) * 256
                                          + warp_n * 128 + p * 32 + nbyteB);
                ldsm_x4_trans(bf[p], bB + SWZ256(off));
            }
#pragma unroll
            for (int mb = 0; mb < 2; mb++)
#pragma unroll
                for (int nb = 0; nb < 8; nb++)
                    mma16816(acc[mb][nb], af[mb],
                             bf[nb >> 1][(nb & 1) * 2], bf[nb >> 1][(nb & 1) * 2 + 1]);
        }
    }

    const float scale = 0.0625f;
    const int rbase = m0 + warp_m * 32 + (lid >> 2);
    const int cbase = n0 + warp_n * 64 + (lid & 3) * 2;
#pragma unroll
    for (int mb = 0; mb < 2; mb++) {
#pragma unroll
        for (int nb = 0; nb < 8; nb++) {
            int q = cbase + nb * 8;
            if (q < QTOT) {
                int r0 = rbase + mb * 16;
                __half* c0p = g_corrh + ((size_t)b * PTOT + r0) * QTOT + q;
                __half* c1p = c0p + (size_t)8 * QTOT;
                *(__half2*)c0p = __floats2half2_rn(acc[mb][nb][0] * scale,
                                                   acc[mb][nb][1] * scale);
                *(__half2*)c1p = __floats2half2_rn(acc[mb][nb][2] * scale,
                                                   acc[mb][nb][3] * scale);
            }
        }
    }
}

// ---------------------------------------------------------------------------
// Kernel 3: sampler. 256-thr block = 8 warps = 8 n-heads of one (b,h,w).
// Patch stored as overlapping half2 pairs: pairs[r][x] = (v[x], v[x+1]).
// Phase 2: 1 LDS.32 per x-corner-pair per row -> 2 patch LDS per output.
// Pair rows: 20 half2 = 80 B (16B-aligned STS.128, 20-bank row spread).
// grid 8192.
// ---------------------------------------------------------------------------
#define PPITCH 20   // half2 units per pair row (80 B)
__global__ __launch_bounds__(256) void sample_kernel(const float* __restrict__ coords,
                                                     float* __restrict__ out) {
    const int warp = threadIdx.x >> 5;          // = n (0..7)
    const int lane = threadIdx.x & 31;
    const int bhw = blockIdx.x;                  // b*4096 + h*64 + w
    const int b = bhw >> 12;
    const int hw = bhw & 4095;
    const int h = hw >> 6;
    const int w = hw & 63;
    const int n = warp;
    const int qid = ((b * NN + n) << 12) | hw;

    __shared__ uint32_t pairs[8][4][10][PPITCH]; // half2 (v[x], v[x+1])
    __shared__ float2 xdat[8][4][9];             // {fx, x0*4 (bytes, relative)}
    __shared__ float2 ydat[8][4][9];             // {fy, abs y0 | abs y1 <<16}

    const float cx = coords[((((size_t)b * NN + n) * 2 + 0) * HH + h) * WW + w];
    const float cy = coords[((((size_t)b * NN + n) * 2 + 1) * HH + h) * WW + w];

    const __half* corrRow = g_corrh + ((size_t)b * PTOT + hw) * QTOT;
    float* outBase = out + (size_t)qid * 324;

    const int   lvl_off[4] = {0, 4096, 5120, 5376};
    const int   wl[4]      = {64, 32, 16, 8};
    const float inv[4]     = {1.f, 0.5f, 0.25f, 0.125f};

    // Phase 1: patch pair construction + separable metadata
#pragma unroll
    for (int lvl = 0; lvl < 4; lvl++) {
        const int   w2  = wl[lvl];
        const float wm1 = (float)(w2 - 1);
        const float cxs = cx * inv[lvl];
        const float cys = cy * inv[lvl];
        const float ylo = fminf(fmaxf(cys - 4.f, 0.f), wm1);
        const float yhi = fminf(fmaxf(cys + 4.f, 0.f), wm1);
        const float xlo = fminf(fmaxf(cxs - 4.f, 0.f), wm1);
        const int xstart = (int)floorf(xlo);
        const int ystart = (int)floorf(ylo);
        const int yend   = min((int)floorf(yhi) + 1, w2 - 1);
        const int xs4    = xstart & ~3;

        const __half* lbase = corrRow + lvl_off[lvl];
#pragma unroll
        for (int s = 0; s < 2; s++) {
            int slot = lane + s * 32;
            int r = slot >> 2, cb = slot & 3;
            int col = xs4 + cb * 4;
            uint2 v = make_uint2(0u, 0u);        // zero-init: edges stay finite
            if (slot < 40 && r <= yend - ystart && col < w2)
                v = *(const uint2*)(lbase + (ystart + r) * w2 + col);
            // neighbor chunk's first half (valid for cb<3; cb==3 pair unread)
            uint32_t nxt = __shfl_down_sync(0xffffffffu, v.x, 1);
            uint32_t p0 = v.x;                              // (h0,h1)
            uint32_t p1 = (v.x >> 16) | (v.y << 16);        // (h1,h2)
            uint32_t p2 = v.y;                              // (h2,h3)
            uint32_t p3 = (v.y >> 16) | (nxt << 16);        // (h3,next h0)
            if (slot < 40)
                *(uint4*)&pairs[warp][lvl][r][cb * 4] = make_uint4(p0, p1, p2, p3);
        }
        // metadata: lanes 0-8 -> x (relative pair byte offset), 16-24 -> y (abs)
        {
            int grp = lane >> 4;
            int off = lane & 15;
            if (off < 9 && grp < 2) {
                float c   = grp ? cys : cxs;
                int   sub = grp ? ystart : xs4;
                int   str = grp ? (PPITCH * 4) : 4;
                int   bas = grp ? (warp * 4 + lvl) * (10 * PPITCH * 4) : 0;
                float v   = fminf(fmaxf(c + (float)(off - 4), 0.f), wm1);
                float v0f = floorf(v);
                float f   = v - v0f;
                int   i0  = (int)v0f;
                uint32_t packed;
                if (grp) {
                    int i1 = min(i0 + 1, w2 - 1);
                    packed = (uint32_t)(bas + (i0 - sub) * str)
                           | ((uint32_t)(bas + (i1 - sub) * str) << 16);
                } else {
                    packed = (uint32_t)((i0 - sub) * str);  // pair covers x0,x1
                }
                float2 md = make_float2(f, __uint_as_float(packed));
                if (grp) ydat[warp][lvl][off] = md;
                else     xdat[warp][lvl][off] = md;
            }
        }
    }
    __syncwarp();

    // Phase 2: pair-based separable bilinear (2 patch LDS.32 per output)
    const char* pbase = (const char*)&pairs[0][0][0][0];
#pragma unroll
    for (int s = 0; s < 3; s++) {
        int t = lane + s * 32;
        if (t < 81) {
            int ix = t / 9;
            int iy = t - ix * 9;
#pragma unroll
            for (int lvl = 0; lvl < 4; lvl++) {
                float2 xd = xdat[warp][lvl][ix];
                float2 yd = ydat[warp][lvl][iy];
                uint32_t xo = __float_as_uint(xd.y);
                uint32_t yp = __float_as_uint(yd.y);
                uint32_t pa = *(const uint32_t*)(pbase + (yp & 0xFFFFu) + xo);
                uint32_t pc = *(const uint32_t*)(pbase + (yp >> 16) + xo);
                float2 a = __half22float2(*(__half2*)&pa);   // (v00, v01)
                float2 c2 = __half22float2(*(__half2*)&pc);  // (v10, v11)
                float h0 = fmaf(xd.x, a.y - a.x, a.x);
                float h1 = fmaf(xd.x, c2.y - c2.x, c2.x);
                outBase[lvl * 81 + t] = fmaf(yd.x, h1 - h0, h0);
            }
        }
    }
}

// ---------------------------------------------------------------------------
// Launch
// ---------------------------------------------------------------------------
extern "C" void kernel_launch(void* const* d_in, const int* in_sizes, int n_in,
                              void* d_out, int out_size) {
    const float* f1     = (const float*)d_in[0];
    const float* f2     = (const float*)d_in[1];
    const float* coords = (const float*)d_in[2];
    float* out          = (float*)d_out;

    prep_kernel<<<512 + 1024, 256>>>(f2, f1);

    cudaFuncSetAttribute(gemm_kernel, cudaFuncAttributeMaxDynamicSharedMemorySize, GEMM_SMEM);
    gemm_kernel<<<dim3(QPAD / 128, PTOT / 128, Bb), GT, GEMM_SMEM>>>();

    sample_kernel<<<Bb * HH * WW, 256>>>(coords, out);
}